// round 13
// baseline (speedup 1.0000x reference)
#include <cuda_runtime.h>
#include <cstdint>

#define Bb 2
#define Ss 2048
#define Dd 1024
#define Hh 16
#define HDd 64
#define QKV_ELEMS (Bb*Hh*Ss*HDd)   // 4194304 halves per tensor
#define QKV_U32 (QKV_ELEMS/2)      // 2097152 u32
#define WT_U32 ((Dd*Dd)/2)         // 524288 u32

// u32 regions: q,k,v (pair-interleaved half), Vq (pair-of-pairs), concat,
// WT x4 (interleaved half), rounded inputs x3 (interleaved half)
#define OFF_QKV 0ull
#define OFF_VP  (3ull*QKV_U32)
#define OFF_CAT (4ull*QKV_U32)
#define OFF_WT  (5ull*QKV_U32)
#define OFF_AR  (5ull*QKV_U32 + 4ull*WT_U32)

static __device__ uint32_t g_scratch[8ull*QKV_U32 + 4ull*WT_U32];

#define QSC 0.18033688011112042f   // log2(e)/8

// ---------------------------------------------------------------------------
__device__ __forceinline__ uint32_t smem_u32(const void* p) {
    uint32_t a;
    asm("{ .reg .u64 t; cvta.to.shared.u64 t, %1; cvt.u32.u64 %0, t; }"
        : "=r"(a) : "l"(p));
    return a;
}
// pack two floats to f16x2: lo -> low 16 bits (PTX: first src -> high half)
__device__ __forceinline__ uint32_t h2pack(float lo, float hi) {
    uint32_t d;
    asm("cvt.rn.f16x2.f32 %0, %1, %2;" : "=r"(d) : "f"(hi), "f"(lo));
    return d;
}
__device__ __forceinline__ void mma_f16(float* c, const uint32_t* a, const uint32_t* b) {
    asm volatile(
        "mma.sync.aligned.m16n8k16.row.col.f32.f16.f16.f32 "
        "{%0,%1,%2,%3}, {%4,%5,%6,%7}, {%8,%9}, {%0,%1,%2,%3};"
        : "+f"(c[0]), "+f"(c[1]), "+f"(c[2]), "+f"(c[3])
        : "r"(a[0]), "r"(a[1]), "r"(a[2]), "r"(a[3]), "r"(b[0]), "r"(b[1]));
}
#define CP16(smem_addr, gptr) \
    asm volatile("cp.async.ca.shared.global [%0], [%1], 16;" \
                 :: "r"(smem_addr), "l"(gptr) : "memory")
#define CPCOMMIT() asm volatile("cp.async.commit_group;" ::: "memory")
#define CPWAIT(N)  asm volatile("cp.async.wait_group %0;" :: "n"(N) : "memory")

// ---------------------------------------------------------------------------
// Prep: fp32 -> f16x2, pair-interleaved within each 16-half k-group:
// phys u32 pos p holds half-pair q=(p>>1)+(p&1)*4, i.e. halves (2q,2q+1).
// ---------------------------------------------------------------------------
__global__ __launch_bounds__(256) void round_inputs_kernel(
    const float* __restrict__ q, const float* __restrict__ k,
    const float* __restrict__ v)
{
    const int z = blockIdx.y;
    const float* in = (z == 0) ? q : ((z == 1) ? k : v);
    uint32_t* out = g_scratch + OFF_AR + (size_t)z * QKV_U32;
    const size_t i = ((size_t)blockIdx.x * 256 + threadIdx.x) * 16;
    float vv[16];
#pragma unroll
    for (int j = 0; j < 16; j += 4)
        *(float4*)&vv[j] = *(const float4*)(in + i + j);
    const size_t ob = i >> 1;
#pragma unroll
    for (int p = 0; p < 8; p++) {
        const int qq = (p >> 1) + (p & 1) * 4;
        out[ob + p] = h2pack(vv[2 * qq], vv[2 * qq + 1]);
    }
}

// Weight transpose + half + pair-interleave; Wq additionally scaled by QSC.
__global__ __launch_bounds__(256) void transpose_w_kernel(
    const float* __restrict__ Wq, const float* __restrict__ Wk,
    const float* __restrict__ Wv, const float* __restrict__ Wo)
{
    __shared__ float t[32][33];
    const int z = blockIdx.z;
    const float* W = (z == 0) ? Wq : ((z == 1) ? Wk : ((z == 2) ? Wv : Wo));
    uint32_t* WT = g_scratch + OFF_WT + (size_t)z * WT_U32;
    const int x0 = blockIdx.x * 32, y0 = blockIdx.y * 32;
    const int tx = threadIdx.x, ty = threadIdx.y;
#pragma unroll
    for (int j = 0; j < 32; j += 8)
        t[ty + j][tx] = W[(size_t)(y0 + ty + j) * Dd + x0 + tx];
    __syncthreads();
    const float sc = (z == 0) ? QSC : 1.0f;
#pragma unroll
    for (int uu = 0; uu < 2; uu++) {
        const int u = ty * 2 + uu;               // u32 col within 16 (2 groups)
        const int g = u >> 3, p = u & 7;
        const int qq = (p >> 1) + (p & 1) * 4;
        const int k0 = g * 16 + 2 * qq;          // k-local half index
        const float a = t[k0][tx] * sc, b = t[k0 + 1][tx] * sc;
        WT[(size_t)(x0 + tx) * (Dd / 2) + (y0 >> 1) + u] = h2pack(a, b);
    }
}

// ---------------------------------------------------------------------------
// fp16 mma GEMM: CTA 256x128, warp 64x64 (8 warps 4x2), BK=32 halves (16 u32),
// 8-stage cp.async pipeline, packed stride-16-u32 tiles + ks-swap -> LDS.64.
// ---------------------------------------------------------------------------
#define GTA_U (256 * 16)          // 4096 u32
#define GTB_U (128 * 16)          // 2048
#define GSTAGE_U (GTA_U + GTB_U)  // 6144
#define GNSTAGE 8
#define GEMM_SMEM_BYTES (GNSTAGE * GSTAGE_U * 4)   // 196608

template<int SPLIT>
__device__ __forceinline__ void gemm_mma(const uint32_t* __restrict__ A,
                                         const uint32_t* __restrict__ BT,
                                         const float* __restrict__ bias,
                                         float bsc, void* __restrict__ Cv)
{
    extern __shared__ uint32_t smu[];

    const int tid = threadIdx.x;
    const int wid = tid >> 5, lane = tid & 31;
    const int m0 = blockIdx.y * 256, n0 = blockIdx.x * 128;

    const int row0 = tid >> 2, c4 = tid & 3;
    const int swp = ((c4 >> 1) ^ ((row0 >> 1) & 1)) << 3;
    const uint32_t soBase = (uint32_t)(row0 * 16 + swp + (c4 & 1) * 4) * 4;
    const uint32_t soStep = 64 * 16 * 4;
    const uint32_t* gA0 = A  + (size_t)(m0 + row0) * 512 + c4 * 4;
    const uint32_t* gA1 = A  + (size_t)(m0 + row0 + 64) * 512 + c4 * 4;
    const uint32_t* gA2 = A  + (size_t)(m0 + row0 + 128) * 512 + c4 * 4;
    const uint32_t* gA3 = A  + (size_t)(m0 + row0 + 192) * 512 + c4 * 4;
    const uint32_t* gB0 = BT + (size_t)(n0 + row0) * 512 + c4 * 4;
    const uint32_t* gB1 = BT + (size_t)(n0 + row0 + 64) * 512 + c4 * 4;
    const uint32_t sbase = smem_u32(smu);

    const int wm = wid >> 1, wn = wid & 1;
    const int mbw = wm * 64, nbw = wn * 64;
    const int gr = lane >> 2, ck = lane & 3;

    float acc[4][8][4];
#pragma unroll
    for (int i = 0; i < 4; i++)
#pragma unroll
        for (int j = 0; j < 8; j++)
#pragma unroll
            for (int r = 0; r < 4; r++) acc[i][j][r] = 0.f;

#define GISSUE(buf, k0) do { \
        uint32_t a_ = sbase + (uint32_t)(buf) * (GSTAGE_U * 4); \
        uint32_t b_ = a_ + GTA_U * 4; \
        CP16(a_ + soBase,            gA0 + (k0)); \
        CP16(a_ + soBase + soStep,   gA1 + (k0)); \
        CP16(a_ + soBase + 2*soStep, gA2 + (k0)); \
        CP16(a_ + soBase + 3*soStep, gA3 + (k0)); \
        CP16(b_ + soBase,            gB0 + (k0)); \
        CP16(b_ + soBase + soStep,   gB1 + (k0)); \
        CPCOMMIT(); \
    } while (0)

    GISSUE(0, 0); GISSUE(1, 16); GISSUE(2, 32); GISSUE(3, 48);
    GISSUE(4, 64); GISSUE(5, 80); GISSUE(6, 96);

    const int NIT = 32;   // 1024 halves / 32 per iter
    const int swk = (gr >> 1) & 1;
    for (int it = 0; it < NIT; ++it) {
        CPWAIT(6);
        __syncthreads();
        if (it + 7 < NIT) GISSUE((it + 7) & 7, (it + 7) * 16);
        else CPCOMMIT();

        const uint32_t* SA = smu + (size_t)(it & 7) * GSTAGE_U;
        const uint32_t* SB = SA + GTA_U;
#pragma unroll
        for (int ks = 0; ks < 2; ks++) {
            const int ko = ((ks ^ swk) << 3) + 2 * ck;
            uint2 bfr[8];
#pragma unroll
            for (int nt = 0; nt < 8; nt++)
                bfr[nt] = *(const uint2*)&SB[(nbw + nt * 8 + gr) * 16 + ko];
#pragma unroll
            for (int mt = 0; mt < 4; mt++) {
                const int rb = (mbw + mt * 16 + gr) * 16 + ko;
                const uint2 a01 = *(const uint2*)&SA[rb];
                const uint2 a23 = *(const uint2*)&SA[rb + 8 * 16];
                uint32_t af[4] = {a01.x, a23.x, a01.y, a23.y};
#pragma unroll
                for (int nt = 0; nt < 8; nt++)
                    mma_f16(acc[mt][nt], af, (const uint32_t*)&bfr[nt]);
            }
        }
    }
#undef GISSUE

#pragma unroll
    for (int mt = 0; mt < 4; mt++) {
        const int row = m0 + mbw + mt * 16 + gr;
#pragma unroll
        for (int nt = 0; nt < 8; nt++) {
            const int cbase = n0 + nbw + nt * 8;
            const float2 bi = *(const float2*)(bias + cbase + 2 * ck);
            if (SPLIT) {
                uint32_t* C = (uint32_t*)Cv;
                const int h = cbase >> 6;
                const int dloc = cbase & 63;
                const int g = dloc >> 4;
                const int q_l = ((dloc >> 3) & 1) * 4 + ck;
                const int upos = g * 8 + 2 * (q_l & 3) + (q_l >> 2);
                const int b0_ = row >> 11, s0 = row & 2047;
                const int row1 = row + 8;
                const int b1_ = row1 >> 11, s1 = row1 & 2047;
                C[(((size_t)(b0_ * Hh + h)) * Ss + s0) * 32 + upos] =
                    h2pack(acc[mt][nt][0] + bi.x * bsc,
                           acc[mt][nt][1] + bi.y * bsc);
                C[(((size_t)(b1_ * Hh + h)) * Ss + s1) * 32 + upos] =
                    h2pack(acc[mt][nt][2] + bi.x * bsc,
                           acc[mt][nt][3] + bi.y * bsc);
            } else {
                float* C = (float*)Cv;
                const int col = cbase + 2 * ck;
                float2 v0, v1;
                v0.x = acc[mt][nt][0] + bi.x; v0.y = acc[mt][nt][1] + bi.y;
                v1.x = acc[mt][nt][2] + bi.x; v1.y = acc[mt][nt][3] + bi.y;
                *(float2*)&C[(size_t)row * Dd + col] = v0;
                *(float2*)&C[(size_t)(row + 8) * Dd + col] = v1;
            }
        }
    }
}

__global__ __launch_bounds__(256, 1) void gemm_qkv_mma_kernel(
    const float* __restrict__ bq, const float* __restrict__ bk,
    const float* __restrict__ bv)
{
    const int z = blockIdx.z;
    const uint32_t* A  = g_scratch + OFF_AR + (size_t)z * QKV_U32;
    const float* bias  = (z == 0) ? bq : ((z == 1) ? bk : bv);
    const uint32_t* BT = g_scratch + OFF_WT + (size_t)z * WT_U32;
    uint32_t* C = g_scratch + (size_t)z * QKV_U32;
    gemm_mma<1>(A, BT, bias, (z == 0) ? QSC : 1.0f, C);
}

__global__ __launch_bounds__(256, 1) void gemm_out_mma_kernel(
    const float* __restrict__ bo, float* __restrict__ out)
{
    const uint32_t* A  = g_scratch + OFF_CAT;
    const uint32_t* BT = g_scratch + OFF_WT + 3ull * WT_U32;
    gemm_mma<0>(A, BT, bo, 1.0f, out);
}

// ---------------------------------------------------------------------------
// V repack -> pair-of-pairs: for each 32-key tile T (16 kp-rows), 8 newrows:
//   newrow r (j=r>>2, s=r&3) holds, for d in [0,64):
//     [d*2+0] = Vp[kp = 8j+s][d],  [d*2+1] = Vp[kp = 8j+s+4][d]
//   where Vp[kp][d] = (half d of key 2kp) | (half d of key 2kp+1)<<16.
// Input V is [B,H,S,32u32] with d-interleaved halves.
// ---------------------------------------------------------------------------
__global__ __launch_bounds__(256) void repack_v_kernel()
{
    const uint32_t* in = g_scratch + 2ull * QKV_U32;   // V
    uint32_t* out = g_scratch + OFF_VP;
    const size_t o = (size_t)blockIdx.x * 256 + threadIdx.x;  // over QKV_U32
    const int bh = (int)(o >> 16);           // 65536 u32 per bh
    const int rem = (int)(o & 65535);
    const int T = rem >> 10;                 // 1024 u32 per tile
    const int r = (rem >> 7) & 7;
    const int d2 = rem & 127;
    const int d = d2 >> 1, p = d2 & 1;
    const int j = r >> 2, s = r & 3;
    const int kp = T * 16 + j * 8 + s + p * 4;
    // locate half d within the 32-u32 interleaved row
    const int g = d >> 4, hh = d & 15, qh = hh >> 1, sel = hh & 1;
    const int u = g * 8 + 2 * (qh & 3) + (qh >> 2);
    const size_t rbase = ((size_t)bh * Ss + 2 * kp) * 32 + u;
    const uint32_t X = in[rbase];            // key 2kp
    const uint32_t Y = in[rbase + 32];       // key 2kp+1
    const uint32_t lo = sel ? (X >> 16) : (X & 0xFFFFu);
    const uint32_t hi = sel ? (Y & 0xFFFF0000u) : (Y << 16);
    out[o] = lo | hi;
}

// ---------------------------------------------------------------------------
// fp16 MMA flash attention, causal, intra-warp pipelined (QK i+1 overlaps
// softmax+PV of i). P fed to PV via direct f16x2 packing. V in pair-of-pairs
// layout -> LDS.64 fragment loads (stride 144 = bank-bijective). 3 CTAs/SM.
// ---------------------------------------------------------------------------
#define QST 40                        // Q/K row stride (u32)
#define SQ_U (128 * QST)              // 5120
#define SK_OFF SQ_U
#define SKB2 (32 * QST)               // 1280
#define VST3 144                      // V newrow stride (u32)
#define SV_OFF (SK_OFF + 2 * SKB2)    // 7680
#define SVB (8 * VST3)                // 1152
#define ATTN_SMEM_BYTES ((SV_OFF + 3 * SVB) * 4)   // 44544

__global__ __launch_bounds__(128, 3) void attn_mma_kernel()
{
    extern __shared__ uint32_t smu[];
    const int bx = blockIdx.x;
    const int qt = 15 - (bx >> 5);
    const int bh = bx & 31;
    const int q0 = qt * 128;
    const int tid = threadIdx.x;
    const int wq = tid >> 5, lane = tid & 31;
    const int gr = lane >> 2, tg = lane & 3;

    const uint32_t* Qp = g_scratch + ((size_t)bh * Ss + q0) * 32;
    const uint32_t* Kp = g_scratch + QKV_U32 + (size_t)bh * Ss * 32;
    const uint32_t* Vp = g_scratch + OFF_VP + (size_t)bh * 65536;

    const uint32_t smb = smem_u32(smu);

#define KISSUE(kbuf, vbuf, t0) do { \
        _Pragma("unroll") \
        for (int j_ = 0; j_ < 2; j_++) { \
            const int f_ = tid + j_ * 128; \
            const int rK = f_ >> 3; const int cK = (f_ & 7) * 4; \
            CP16(smb + (uint32_t)(SK_OFF + (kbuf)*SKB2 + rK*QST + cK) * 4, \
                 Kp + (size_t)((t0) + rK) * 32 + cK); \
            const int rV = f_ >> 5; const int cV = (f_ & 31) * 4; \
            CP16(smb + (uint32_t)(SV_OFF + (vbuf)*SVB + rV*VST3 + cV) * 4, \
                 Vp + (size_t)(((t0) >> 5) * 8 + rV) * 128 + cV); \
        } \
        CPCOMMIT(); \
    } while (0)

#define QK_TILE(S, kbuf) do { \
        const uint32_t* K_ = smu + SK_OFF + (kbuf) * SKB2; \
        const uint32_t* Q_ = smu; \
        _Pragma("unroll") \
        for (int mt_ = 0; mt_ < 2; mt_++) \
            _Pragma("unroll") \
            for (int nt_ = 0; nt_ < 4; nt_++) \
                _Pragma("unroll") \
                for (int r_ = 0; r_ < 4; r_++) S[mt_][nt_][r_] = 0.f; \
        _Pragma("unroll") \
        for (int kt_ = 0; kt_ < 4; kt_++) { \
            const int ko_ = kt_ * 8 + 2 * tg; \
            uint2 bkf_[4]; \
            _Pragma("unroll") \
            for (int nt_ = 0; nt_ < 4; nt_++) \
                bkf_[nt_] = *(const uint2*)&K_[(nt_ * 8 + gr) * QST + ko_]; \
            _Pragma("unroll") \
            for (int mt_ = 0; mt_ < 2; mt_++) { \
                const int rr_ = wq * 32 + mt_ * 16 + gr; \
                const uint2 a01_ = *(const uint2*)&Q_[rr_ * QST + ko_]; \
                const uint2 a23_ = *(const uint2*)&Q_[(rr_ + 8) * QST + ko_]; \
                uint32_t aq_[4] = {a01_.x, a23_.x, a01_.y, a23_.y}; \
                _Pragma("unroll") \
                for (int nt_ = 0; nt_ < 4; nt_++) \
                    mma_f16(S[mt_][nt_], aq_, (const uint32_t*)&bkf_[nt_]); \
            } \
        } \
    } while (0)

    // stage Q (8 chunks/thread) then first K/V tile
    {
#pragma unroll
        for (int j = 0; j < 8; j++) {
            const int f = tid + j * 128;
            const int r = f >> 3, c = (f & 7) * 4;
            CP16(smb + (uint32_t)(r * QST + c) * 4, Qp + (size_t)r * 32 + c);
        }
        CPCOMMIT();
    }
    KISSUE(0, 0, 0);

    float Of[2][8][4];
#pragma unroll
    for (int mt = 0; mt < 2; mt++)
#pragma unroll
        for (int nt = 0; nt < 8; nt++)
#pragma unroll
            for (int r = 0; r < 4; r++) Of[mt][nt][r] = 0.f;
    float m_[2][2] = {{-1e30f, -1e30f}, {-1e30f, -1e30f}};
    float l_[2][2] = {{0.f, 0.f}, {0.f, 0.f}};
    float Sc[2][4][4], Sn[2][4][4];

    const int ntiles = qt * 4 + 4;
    const int my_last = qt * 4 + wq;

    CPWAIT(0);
    __syncthreads();
    KISSUE(1, 1, 32);
    QK_TILE(Sc, 0);

    for (int it = 0; it < ntiles; it++) {
        CPWAIT(0);
        __syncthreads();
        if (it + 2 < ntiles) KISSUE((it + 2) & 1, (it + 2) % 3, (it + 2) * 32);

        const bool more = (it + 1 < ntiles) && (it + 1 <= my_last);
        if (more) QK_TILE(Sn, (it + 1) & 1);

        if (it <= my_last) {
            if (it == my_last) {
                const int t0k = it * 32;
#pragma unroll
                for (int mt = 0; mt < 2; mt++) {
                    const int r0 = q0 + wq * 32 + mt * 16 + gr;
#pragma unroll
                    for (int nt = 0; nt < 4; nt++) {
                        const int key = t0k + nt * 8 + 2 * tg;
                        if (key > r0)         Sc[mt][nt][0] = -1e30f;
                        if (key + 1 > r0)     Sc[mt][nt][1] = -1e30f;
                        if (key > r0 + 8)     Sc[mt][nt][2] = -1e30f;
                        if (key + 1 > r0 + 8) Sc[mt][nt][3] = -1e30f;
                    }
                }
            }

            // online softmax (log2 domain, fp32)
#pragma unroll
            for (int mt = 0; mt < 2; mt++)
#pragma unroll
                for (int h = 0; h < 2; h++) {
                    float tm = fmaxf(fmaxf(Sc[mt][0][2*h], Sc[mt][0][2*h+1]),
                                     fmaxf(Sc[mt][1][2*h], Sc[mt][1][2*h+1]));
                    tm = fmaxf(tm, fmaxf(fmaxf(Sc[mt][2][2*h], Sc[mt][2][2*h+1]),
                                         fmaxf(Sc[mt][3][2*h], Sc[mt][3][2*h+1])));
                    tm = fmaxf(tm, __shfl_xor_sync(0xffffffffu, tm, 1));
                    tm = fmaxf(tm, __shfl_xor_sync(0xffffffffu, tm, 2));
                    const float mnew = fmaxf(m_[mt][h], tm);
                    const float corr = exp2f(m_[mt][h] - mnew);
                    m_[mt][h] = mnew;
                    l_[mt][h] *= corr;
#pragma unroll
                    for (int nt = 0; nt < 8; nt++) {
                        Of[mt][nt][2*h]     *= corr;
                        Of[mt][nt][2*h + 1] *= corr;
                    }
                }

            float rs[2][2] = {{0.f, 0.f}, {0.f, 0.f}};
#pragma unroll
            for (int mt = 0; mt < 2; mt++)
#pragma unroll
                for (int nt = 0; nt < 4; nt++) {
                    const float p0 = exp2f(Sc[mt][nt][0] - m_[mt][0]);
                    const float p1 = exp2f(Sc[mt][nt][1] - m_[mt][0]);
                    const float p2 = exp2f(Sc[mt][nt][2] - m_[mt][1]);
                    const float p3 = exp2f(Sc[mt][nt][3] - m_[mt][1]);
                    rs[mt][0] += p0 + p1;
                    rs[mt][1] += p2 + p3;
                    Sc[mt][nt][0] = p0; Sc[mt][nt][1] = p1;
                    Sc[mt][nt][2] = p2; Sc[mt][nt][3] = p3;
                }
#pragma unroll
            for (int mt = 0; mt < 2; mt++)
#pragma unroll
                for (int h = 0; h < 2; h++) {
                    float r = rs[mt][h];
                    r += __shfl_xor_sync(0xffffffffu, r, 1);
                    r += __shfl_xor_sync(0xffffffffu, r, 2);
                    l_[mt][h] += r;
                }

            // P @ V : P packed straight from C-fragments; V rows pair-packed
            const uint32_t* V_ = smu + SV_OFF + (it % 3) * SVB;
#pragma unroll
            for (int j = 0; j < 2; j++) {
                uint32_t ap[2][4];
#pragma unroll
                for (int mt = 0; mt < 2; mt++) {
                    ap[mt][0] = h2pack(Sc[mt][2*j][0],   Sc[mt][2*j][1]);
                    ap[mt][1] = h2pack(Sc[mt][2*j][2],   Sc[mt][2*j][3]);
                    ap[mt][2] = h2pack(Sc[mt][2*j+1][0], Sc[mt][2*j+1][1]);
                    ap[mt][3] = h2pack(Sc[mt][2*j+1][2], Sc[mt][2*j+1][3]);
                }
#pragma unroll
                for (int ntd = 0; ntd < 8; ntd++) {
                    const uint2 vv = *(const uint2*)
                        &V_[(j * 4 + tg) * VST3 + (ntd * 8 + gr) * 2];
                    mma_f16(Of[0][ntd], ap[0], (const uint32_t*)&vv);
                    mma_f16(Of[1][ntd], ap[1], (const uint32_t*)&vv);
                }
            }
        }

#pragma unroll
        for (int mt = 0; mt < 2; mt++)
#pragma unroll
            for (int nt = 0; nt < 4; nt++)
#pragma unroll
                for (int r = 0; r < 4; r++) Sc[mt][nt][r] = Sn[mt][nt][r];
    }
#undef KISSUE
#undef QK_TILE

    // epilogue -> concat, half pair-interleaved along d
    float inv[2][2];
#pragma unroll
    for (int mt = 0; mt < 2; mt++) {
        inv[mt][0] = 1.f / l_[mt][0];
        inv[mt][1] = 1.f / l_[mt][1];
    }
    const int b_ = bh >> 4, h_ = bh & 15;
#pragma unroll
    for (int mt = 0; mt < 2; mt++) {
        const int r0 = q0 + wq * 32 + mt * 16 + gr;
        uint32_t* o0 = g_scratch + OFF_CAT + ((size_t)(b_ * Ss + r0)) * 512 + h_ * 32;
        uint32_t* o1 = g_scratch + OFF_CAT + ((size_t)(b_ * Ss + r0 + 8)) * 512 + h_ * 32;
#pragma unroll
        for (int ntd = 0; ntd < 8; ntd++) {
            const int q_l = (ntd & 1) * 4 + tg;
            const int upos = (ntd >> 1) * 8 + 2 * (q_l & 3) + (q_l >> 2);
            o0[upos] = h2pack(Of[mt][ntd][0] * inv[mt][0],
                              Of[mt][ntd][1] * inv[mt][0]);
            o1[upos] = h2pack(Of[mt][ntd][2] * inv[mt][1],
                              Of[mt][ntd][3] * inv[mt][1]);
        }
    }
}

// ---------------------------------------------------------------------------
extern "C" void kernel_launch(void* const* d_in, const int* in_sizes, int n_in,
                              void* d_out, int out_size)
{
    const float* q_in = (const float*)d_in[0];
    const float* k_in = (const float*)d_in[1];
    const float* v_in = (const float*)d_in[2];
    const float* Wq   = (const float*)d_in[3];
    const float* bq   = (const float*)d_in[4];
    const float* Wk   = (const float*)d_in[5];
    const float* bk   = (const float*)d_in[6];
    const float* Wv   = (const float*)d_in[7];
    const float* bv   = (const float*)d_in[8];
    const float* Wo   = (const float*)d_in[9];
    const float* bo   = (const float*)d_in[10];
    float* out = (float*)d_out;

    cudaFuncSetAttribute(gemm_qkv_mma_kernel,
                         cudaFuncAttributeMaxDynamicSharedMemorySize, GEMM_SMEM_BYTES);
    cudaFuncSetAttribute(gemm_out_mma_kernel,
                         cudaFuncAttributeMaxDynamicSharedMemorySize, GEMM_SMEM_BYTES);
    cudaFuncSetAttribute(attn_mma_kernel,
                         cudaFuncAttributeMaxDynamicSharedMemorySize, ATTN_SMEM_BYTES);

    round_inputs_kernel<<<dim3(QKV_ELEMS / 4096, 3), 256>>>(q_in, k_in, v_in);
    transpose_w_kernel<<<dim3(32, 32, 4), dim3(32, 8)>>>(Wq, Wk, Wv, Wo);

    gemm_qkv_mma_kernel<<<dim3(8, 16, 3), 256, GEMM_SMEM_BYTES>>>(bq, bk, bv);

    repack_v_kernel<<<QKV_U32 / 256, 256>>>();

    attn_mma_kernel<<<512, 128, ATTN_SMEM_BYTES>>>();

    gemm_out_mma_kernel<<<dim3(8, 16), 256, GEMM_SMEM_BYTES>>>(bo, out);
}

// round 14
// speedup vs baseline: 1.0908x; 1.0908x over previous
#include <cuda_runtime.h>
#include <cstdint>

#define Bb 2
#define Ss 2048
#define Dd 1024
#define Hh 16
#define HDd 64
#define QKV_ELEMS (Bb*Hh*Ss*HDd)   // 4194304 halves per tensor
#define QKV_U32 (QKV_ELEMS/2)      // 2097152 u32
#define WT_U32 ((Dd*Dd)/2)         // 524288 u32

// u32 regions: q,k,v (pair-interleaved half), Vq (pair-of-pairs), concat,
// WT x4 (interleaved half), rounded inputs x3 (interleaved half)
#define OFF_QKV 0ull
#define OFF_VP  (3ull*QKV_U32)
#define OFF_CAT (4ull*QKV_U32)
#define OFF_WT  (5ull*QKV_U32)
#define OFF_AR  (5ull*QKV_U32 + 4ull*WT_U32)

static __device__ uint32_t g_scratch[8ull*QKV_U32 + 4ull*WT_U32];

#define QSC 0.18033688011112042f   // log2(e)/8

// ---------------------------------------------------------------------------
__device__ __forceinline__ uint32_t smem_u32(const void* p) {
    uint32_t a;
    asm("{ .reg .u64 t; cvta.to.shared.u64 t, %1; cvt.u32.u64 %0, t; }"
        : "=r"(a) : "l"(p));
    return a;
}
// pack two floats to f16x2: lo -> low 16 bits (PTX: first src -> high half)
__device__ __forceinline__ uint32_t h2pack(float lo, float hi) {
    uint32_t d;
    asm("cvt.rn.f16x2.f32 %0, %1, %2;" : "=r"(d) : "f"(hi), "f"(lo));
    return d;
}
__device__ __forceinline__ void mma_f16(float* c, const uint32_t* a, const uint32_t* b) {
    asm volatile(
        "mma.sync.aligned.m16n8k16.row.col.f32.f16.f16.f32 "
        "{%0,%1,%2,%3}, {%4,%5,%6,%7}, {%8,%9}, {%0,%1,%2,%3};"
        : "+f"(c[0]), "+f"(c[1]), "+f"(c[2]), "+f"(c[3])
        : "r"(a[0]), "r"(a[1]), "r"(a[2]), "r"(a[3]), "r"(b[0]), "r"(b[1]));
}
#define CP16(smem_addr, gptr) \
    asm volatile("cp.async.ca.shared.global [%0], [%1], 16;" \
                 :: "r"(smem_addr), "l"(gptr) : "memory")
#define CPCOMMIT() asm volatile("cp.async.commit_group;" ::: "memory")
#define CPWAIT(N)  asm volatile("cp.async.wait_group %0;" :: "n"(N) : "memory")

// ---------------------------------------------------------------------------
// Prep: fp32 -> f16x2, pair-interleaved within each 16-half k-group:
// phys u32 pos p holds half-pair q=(p>>1)+(p&1)*4, i.e. halves (2q,2q+1).
// ---------------------------------------------------------------------------
__global__ __launch_bounds__(256) void round_inputs_kernel(
    const float* __restrict__ q, const float* __restrict__ k,
    const float* __restrict__ v)
{
    const int z = blockIdx.y;
    const float* in = (z == 0) ? q : ((z == 1) ? k : v);
    uint32_t* out = g_scratch + OFF_AR + (size_t)z * QKV_U32;
    const size_t i = ((size_t)blockIdx.x * 256 + threadIdx.x) * 16;
    float vv[16];
#pragma unroll
    for (int j = 0; j < 16; j += 4)
        *(float4*)&vv[j] = *(const float4*)(in + i + j);
    const size_t ob = i >> 1;
#pragma unroll
    for (int p = 0; p < 8; p++) {
        const int qq = (p >> 1) + (p & 1) * 4;
        out[ob + p] = h2pack(vv[2 * qq], vv[2 * qq + 1]);
    }
}

// Weight transpose + half + pair-interleave; Wq additionally scaled by QSC.
__global__ __launch_bounds__(256) void transpose_w_kernel(
    const float* __restrict__ Wq, const float* __restrict__ Wk,
    const float* __restrict__ Wv, const float* __restrict__ Wo)
{
    __shared__ float t[32][33];
    const int z = blockIdx.z;
    const float* W = (z == 0) ? Wq : ((z == 1) ? Wk : ((z == 2) ? Wv : Wo));
    uint32_t* WT = g_scratch + OFF_WT + (size_t)z * WT_U32;
    const int x0 = blockIdx.x * 32, y0 = blockIdx.y * 32;
    const int tx = threadIdx.x, ty = threadIdx.y;
#pragma unroll
    for (int j = 0; j < 32; j += 8)
        t[ty + j][tx] = W[(size_t)(y0 + ty + j) * Dd + x0 + tx];
    __syncthreads();
    const float sc = (z == 0) ? QSC : 1.0f;
#pragma unroll
    for (int uu = 0; uu < 2; uu++) {
        const int u = ty * 2 + uu;               // u32 col within 16 (2 groups)
        const int g = u >> 3, p = u & 7;
        const int qq = (p >> 1) + (p & 1) * 4;
        const int k0 = g * 16 + 2 * qq;          // k-local half index
        const float a = t[k0][tx] * sc, b = t[k0 + 1][tx] * sc;
        WT[(size_t)(x0 + tx) * (Dd / 2) + (y0 >> 1) + u] = h2pack(a, b);
    }
}

// ---------------------------------------------------------------------------
// fp16 mma GEMM: CTA 256x128, warp 64x64 (8 warps 4x2), BK=32 halves (16 u32),
// 8-stage cp.async pipeline, packed stride-16-u32 tiles + ks-swap -> LDS.64.
// ---------------------------------------------------------------------------
#define GTA_U (256 * 16)          // 4096 u32
#define GTB_U (128 * 16)          // 2048
#define GSTAGE_U (GTA_U + GTB_U)  // 6144
#define GNSTAGE 8
#define GEMM_SMEM_BYTES (GNSTAGE * GSTAGE_U * 4)   // 196608

template<int SPLIT>
__device__ __forceinline__ void gemm_mma(const uint32_t* __restrict__ A,
                                         const uint32_t* __restrict__ BT,
                                         const float* __restrict__ bias,
                                         float bsc, void* __restrict__ Cv)
{
    extern __shared__ uint32_t smu[];

    const int tid = threadIdx.x;
    const int wid = tid >> 5, lane = tid & 31;
    const int m0 = blockIdx.y * 256, n0 = blockIdx.x * 128;

    const int row0 = tid >> 2, c4 = tid & 3;
    const int swp = ((c4 >> 1) ^ ((row0 >> 1) & 1)) << 3;
    const uint32_t soBase = (uint32_t)(row0 * 16 + swp + (c4 & 1) * 4) * 4;
    const uint32_t soStep = 64 * 16 * 4;
    const uint32_t* gA0 = A  + (size_t)(m0 + row0) * 512 + c4 * 4;
    const uint32_t* gA1 = A  + (size_t)(m0 + row0 + 64) * 512 + c4 * 4;
    const uint32_t* gA2 = A  + (size_t)(m0 + row0 + 128) * 512 + c4 * 4;
    const uint32_t* gA3 = A  + (size_t)(m0 + row0 + 192) * 512 + c4 * 4;
    const uint32_t* gB0 = BT + (size_t)(n0 + row0) * 512 + c4 * 4;
    const uint32_t* gB1 = BT + (size_t)(n0 + row0 + 64) * 512 + c4 * 4;
    const uint32_t sbase = smem_u32(smu);

    const int wm = wid >> 1, wn = wid & 1;
    const int mbw = wm * 64, nbw = wn * 64;
    const int gr = lane >> 2, ck = lane & 3;

    float acc[4][8][4];
#pragma unroll
    for (int i = 0; i < 4; i++)
#pragma unroll
        for (int j = 0; j < 8; j++)
#pragma unroll
            for (int r = 0; r < 4; r++) acc[i][j][r] = 0.f;

#define GISSUE(buf, k0) do { \
        uint32_t a_ = sbase + (uint32_t)(buf) * (GSTAGE_U * 4); \
        uint32_t b_ = a_ + GTA_U * 4; \
        CP16(a_ + soBase,            gA0 + (k0)); \
        CP16(a_ + soBase + soStep,   gA1 + (k0)); \
        CP16(a_ + soBase + 2*soStep, gA2 + (k0)); \
        CP16(a_ + soBase + 3*soStep, gA3 + (k0)); \
        CP16(b_ + soBase,            gB0 + (k0)); \
        CP16(b_ + soBase + soStep,   gB1 + (k0)); \
        CPCOMMIT(); \
    } while (0)

    GISSUE(0, 0); GISSUE(1, 16); GISSUE(2, 32); GISSUE(3, 48);
    GISSUE(4, 64); GISSUE(5, 80); GISSUE(6, 96);

    const int NIT = 32;   // 1024 halves / 32 per iter
    const int swk = (gr >> 1) & 1;
    for (int it = 0; it < NIT; ++it) {
        CPWAIT(6);
        __syncthreads();
        if (it + 7 < NIT) GISSUE((it + 7) & 7, (it + 7) * 16);
        else CPCOMMIT();

        const uint32_t* SA = smu + (size_t)(it & 7) * GSTAGE_U;
        const uint32_t* SB = SA + GTA_U;
#pragma unroll
        for (int ks = 0; ks < 2; ks++) {
            const int ko = ((ks ^ swk) << 3) + 2 * ck;
            uint2 bfr[8];
#pragma unroll
            for (int nt = 0; nt < 8; nt++)
                bfr[nt] = *(const uint2*)&SB[(nbw + nt * 8 + gr) * 16 + ko];
#pragma unroll
            for (int mt = 0; mt < 4; mt++) {
                const int rb = (mbw + mt * 16 + gr) * 16 + ko;
                const uint2 a01 = *(const uint2*)&SA[rb];
                const uint2 a23 = *(const uint2*)&SA[rb + 8 * 16];
                uint32_t af[4] = {a01.x, a23.x, a01.y, a23.y};
#pragma unroll
                for (int nt = 0; nt < 8; nt++)
                    mma_f16(acc[mt][nt], af, (const uint32_t*)&bfr[nt]);
            }
        }
    }
#undef GISSUE

#pragma unroll
    for (int mt = 0; mt < 4; mt++) {
        const int row = m0 + mbw + mt * 16 + gr;
#pragma unroll
        for (int nt = 0; nt < 8; nt++) {
            const int cbase = n0 + nbw + nt * 8;
            const float2 bi = *(const float2*)(bias + cbase + 2 * ck);
            if (SPLIT) {
                uint32_t* C = (uint32_t*)Cv;
                const int h = cbase >> 6;
                const int dloc = cbase & 63;
                const int g = dloc >> 4;
                const int q_l = ((dloc >> 3) & 1) * 4 + ck;
                const int upos = g * 8 + 2 * (q_l & 3) + (q_l >> 2);
                const int b0_ = row >> 11, s0 = row & 2047;
                const int row1 = row + 8;
                const int b1_ = row1 >> 11, s1 = row1 & 2047;
                C[(((size_t)(b0_ * Hh + h)) * Ss + s0) * 32 + upos] =
                    h2pack(acc[mt][nt][0] + bi.x * bsc,
                           acc[mt][nt][1] + bi.y * bsc);
                C[(((size_t)(b1_ * Hh + h)) * Ss + s1) * 32 + upos] =
                    h2pack(acc[mt][nt][2] + bi.x * bsc,
                           acc[mt][nt][3] + bi.y * bsc);
            } else {
                float* C = (float*)Cv;
                const int col = cbase + 2 * ck;
                float2 v0, v1;
                v0.x = acc[mt][nt][0] + bi.x; v0.y = acc[mt][nt][1] + bi.y;
                v1.x = acc[mt][nt][2] + bi.x; v1.y = acc[mt][nt][3] + bi.y;
                *(float2*)&C[(size_t)row * Dd + col] = v0;
                *(float2*)&C[(size_t)(row + 8) * Dd + col] = v1;
            }
        }
    }
}

__global__ __launch_bounds__(256, 1) void gemm_qkv_mma_kernel(
    const float* __restrict__ bq, const float* __restrict__ bk,
    const float* __restrict__ bv)
{
    const int z = blockIdx.z;
    const uint32_t* A  = g_scratch + OFF_AR + (size_t)z * QKV_U32;
    const float* bias  = (z == 0) ? bq : ((z == 1) ? bk : bv);
    const uint32_t* BT = g_scratch + OFF_WT + (size_t)z * WT_U32;
    uint32_t* C = g_scratch + (size_t)z * QKV_U32;
    gemm_mma<1>(A, BT, bias, (z == 0) ? QSC : 1.0f, C);
}

__global__ __launch_bounds__(256, 1) void gemm_out_mma_kernel(
    const float* __restrict__ bo, float* __restrict__ out)
{
    const uint32_t* A  = g_scratch + OFF_CAT;
    const uint32_t* BT = g_scratch + OFF_WT + 3ull * WT_U32;
    gemm_mma<0>(A, BT, bo, 1.0f, out);
}

// ---------------------------------------------------------------------------
// V repack -> pair-of-pairs: for each 32-key tile T (16 kp-rows), 8 newrows:
//   newrow r (j=r>>2, s=r&3) holds, for d in [0,64):
//     [d*2+0] = Vp[kp = 8j+s][d],  [d*2+1] = Vp[kp = 8j+s+4][d]
//   where Vp[kp][d] = (half d of key 2kp) | (half d of key 2kp+1)<<16.
// Input V is [B,H,S,32u32] with d-interleaved halves.
// ---------------------------------------------------------------------------
__global__ __launch_bounds__(256) void repack_v_kernel()
{
    const uint32_t* in = g_scratch + 2ull * QKV_U32;   // V
    uint32_t* out = g_scratch + OFF_VP;
    const size_t o = (size_t)blockIdx.x * 256 + threadIdx.x;  // over QKV_U32
    const int bh = (int)(o >> 16);           // 65536 u32 per bh
    const int rem = (int)(o & 65535);
    const int T = rem >> 10;                 // 1024 u32 per tile
    const int r = (rem >> 7) & 7;
    const int d2 = rem & 127;
    const int d = d2 >> 1, p = d2 & 1;
    const int j = r >> 2, s = r & 3;
    const int kp = T * 16 + j * 8 + s + p * 4;
    // locate half d within the 32-u32 interleaved row
    const int g = d >> 4, hh = d & 15, qh = hh >> 1, sel = hh & 1;
    const int u = g * 8 + 2 * (qh & 3) + (qh >> 2);
    const size_t rbase = ((size_t)bh * Ss + 2 * kp) * 32 + u;
    const uint32_t X = in[rbase];            // key 2kp
    const uint32_t Y = in[rbase + 32];       // key 2kp+1
    const uint32_t lo = sel ? (X >> 16) : (X & 0xFFFFu);
    const uint32_t hi = sel ? (Y & 0xFFFF0000u) : (Y << 16);
    out[o] = lo | hi;
}

// ---------------------------------------------------------------------------
// fp16 MMA flash attention, causal, intra-warp pipelined (QK i+1 overlaps
// softmax+PV of i). P fed to PV via direct f16x2 packing. V in pair-of-pairs
// layout -> LDS.64 fragment loads (stride 144 = bank-bijective). 2 CTAs/SM
// (3 CTAs/SM caused ~40 reg spills/thread and a 31us regression in R12).
// ---------------------------------------------------------------------------
#define QST 40                        // Q/K row stride (u32)
#define SQ_U (128 * QST)              // 5120
#define SK_OFF SQ_U
#define SKB2 (32 * QST)               // 1280
#define VST3 144                      // V newrow stride (u32)
#define SV_OFF (SK_OFF + 2 * SKB2)    // 7680
#define SVB (8 * VST3)                // 1152
#define ATTN_SMEM_BYTES ((SV_OFF + 3 * SVB) * 4)   // 44544

__global__ __launch_bounds__(128, 2) void attn_mma_kernel()
{
    extern __shared__ uint32_t smu[];
    const int bx = blockIdx.x;
    const int qt = 15 - (bx >> 5);
    const int bh = bx & 31;
    const int q0 = qt * 128;
    const int tid = threadIdx.x;
    const int wq = tid >> 5, lane = tid & 31;
    const int gr = lane >> 2, tg = lane & 3;

    const uint32_t* Qp = g_scratch + ((size_t)bh * Ss + q0) * 32;
    const uint32_t* Kp = g_scratch + QKV_U32 + (size_t)bh * Ss * 32;
    const uint32_t* Vp = g_scratch + OFF_VP + (size_t)bh * 65536;

    const uint32_t smb = smem_u32(smu);

#define KISSUE(kbuf, vbuf, t0) do { \
        _Pragma("unroll") \
        for (int j_ = 0; j_ < 2; j_++) { \
            const int f_ = tid + j_ * 128; \
            const int rK = f_ >> 3; const int cK = (f_ & 7) * 4; \
            CP16(smb + (uint32_t)(SK_OFF + (kbuf)*SKB2 + rK*QST + cK) * 4, \
                 Kp + (size_t)((t0) + rK) * 32 + cK); \
            const int rV = f_ >> 5; const int cV = (f_ & 31) * 4; \
            CP16(smb + (uint32_t)(SV_OFF + (vbuf)*SVB + rV*VST3 + cV) * 4, \
                 Vp + (size_t)(((t0) >> 5) * 8 + rV) * 128 + cV); \
        } \
        CPCOMMIT(); \
    } while (0)

#define QK_TILE(S, kbuf) do { \
        const uint32_t* K_ = smu + SK_OFF + (kbuf) * SKB2; \
        const uint32_t* Q_ = smu; \
        _Pragma("unroll") \
        for (int mt_ = 0; mt_ < 2; mt_++) \
            _Pragma("unroll") \
            for (int nt_ = 0; nt_ < 4; nt_++) \
                _Pragma("unroll") \
                for (int r_ = 0; r_ < 4; r_++) S[mt_][nt_][r_] = 0.f; \
        _Pragma("unroll") \
        for (int kt_ = 0; kt_ < 4; kt_++) { \
            const int ko_ = kt_ * 8 + 2 * tg; \
            uint2 bkf_[4]; \
            _Pragma("unroll") \
            for (int nt_ = 0; nt_ < 4; nt_++) \
                bkf_[nt_] = *(const uint2*)&K_[(nt_ * 8 + gr) * QST + ko_]; \
            _Pragma("unroll") \
            for (int mt_ = 0; mt_ < 2; mt_++) { \
                const int rr_ = wq * 32 + mt_ * 16 + gr; \
                const uint2 a01_ = *(const uint2*)&Q_[rr_ * QST + ko_]; \
                const uint2 a23_ = *(const uint2*)&Q_[(rr_ + 8) * QST + ko_]; \
                uint32_t aq_[4] = {a01_.x, a23_.x, a01_.y, a23_.y}; \
                _Pragma("unroll") \
                for (int nt_ = 0; nt_ < 4; nt_++) \
                    mma_f16(S[mt_][nt_], aq_, (const uint32_t*)&bkf_[nt_]); \
            } \
        } \
    } while (0)

    // stage Q (8 chunks/thread) then first K/V tile
    {
#pragma unroll
        for (int j = 0; j < 8; j++) {
            const int f = tid + j * 128;
            const int r = f >> 3, c = (f & 7) * 4;
            CP16(smb + (uint32_t)(r * QST + c) * 4, Qp + (size_t)r * 32 + c);
        }
        CPCOMMIT();
    }
    KISSUE(0, 0, 0);

    float Of[2][8][4];
#pragma unroll
    for (int mt = 0; mt < 2; mt++)
#pragma unroll
        for (int nt = 0; nt < 8; nt++)
#pragma unroll
            for (int r = 0; r < 4; r++) Of[mt][nt][r] = 0.f;
    float m_[2][2] = {{-1e30f, -1e30f}, {-1e30f, -1e30f}};
    float l_[2][2] = {{0.f, 0.f}, {0.f, 0.f}};
    float Sc[2][4][4], Sn[2][4][4];

    const int ntiles = qt * 4 + 4;
    const int my_last = qt * 4 + wq;

    CPWAIT(0);
    __syncthreads();
    KISSUE(1, 1, 32);
    QK_TILE(Sc, 0);

    for (int it = 0; it < ntiles; it++) {
        CPWAIT(0);
        __syncthreads();
        if (it + 2 < ntiles) KISSUE((it + 2) & 1, (it + 2) % 3, (it + 2) * 32);

        const bool more = (it + 1 < ntiles) && (it + 1 <= my_last);
        if (more) QK_TILE(Sn, (it + 1) & 1);

        if (it <= my_last) {
            if (it == my_last) {
                const int t0k = it * 32;
#pragma unroll
                for (int mt = 0; mt < 2; mt++) {
                    const int r0 = q0 + wq * 32 + mt * 16 + gr;
#pragma unroll
                    for (int nt = 0; nt < 4; nt++) {
                        const int key = t0k + nt * 8 + 2 * tg;
                        if (key > r0)         Sc[mt][nt][0] = -1e30f;
                        if (key + 1 > r0)     Sc[mt][nt][1] = -1e30f;
                        if (key > r0 + 8)     Sc[mt][nt][2] = -1e30f;
                        if (key + 1 > r0 + 8) Sc[mt][nt][3] = -1e30f;
                    }
                }
            }

            // online softmax (log2 domain, fp32)
#pragma unroll
            for (int mt = 0; mt < 2; mt++)
#pragma unroll
                for (int h = 0; h < 2; h++) {
                    float tm = fmaxf(fmaxf(Sc[mt][0][2*h], Sc[mt][0][2*h+1]),
                                     fmaxf(Sc[mt][1][2*h], Sc[mt][1][2*h+1]));
                    tm = fmaxf(tm, fmaxf(fmaxf(Sc[mt][2][2*h], Sc[mt][2][2*h+1]),
                                         fmaxf(Sc[mt][3][2*h], Sc[mt][3][2*h+1])));
                    tm = fmaxf(tm, __shfl_xor_sync(0xffffffffu, tm, 1));
                    tm = fmaxf(tm, __shfl_xor_sync(0xffffffffu, tm, 2));
                    const float mnew = fmaxf(m_[mt][h], tm);
                    const float corr = exp2f(m_[mt][h] - mnew);
                    m_[mt][h] = mnew;
                    l_[mt][h] *= corr;
#pragma unroll
                    for (int nt = 0; nt < 8; nt++) {
                        Of[mt][nt][2*h]     *= corr;
                        Of[mt][nt][2*h + 1] *= corr;
                    }
                }

            float rs[2][2] = {{0.f, 0.f}, {0.f, 0.f}};
#pragma unroll
            for (int mt = 0; mt < 2; mt++)
#pragma unroll
                for (int nt = 0; nt < 4; nt++) {
                    const float p0 = exp2f(Sc[mt][nt][0] - m_[mt][0]);
                    const float p1 = exp2f(Sc[mt][nt][1] - m_[mt][0]);
                    const float p2 = exp2f(Sc[mt][nt][2] - m_[mt][1]);
                    const float p3 = exp2f(Sc[mt][nt][3] - m_[mt][1]);
                    rs[mt][0] += p0 + p1;
                    rs[mt][1] += p2 + p3;
                    Sc[mt][nt][0] = p0; Sc[mt][nt][1] = p1;
                    Sc[mt][nt][2] = p2; Sc[mt][nt][3] = p3;
                }
#pragma unroll
            for (int mt = 0; mt < 2; mt++)
#pragma unroll
                for (int h = 0; h < 2; h++) {
                    float r = rs[mt][h];
                    r += __shfl_xor_sync(0xffffffffu, r, 1);
                    r += __shfl_xor_sync(0xffffffffu, r, 2);
                    l_[mt][h] += r;
                }

            // P @ V : P packed straight from C-fragments; V rows pair-packed
            const uint32_t* V_ = smu + SV_OFF + (it % 3) * SVB;
#pragma unroll
            for (int j = 0; j < 2; j++) {
                uint32_t ap[2][4];
#pragma unroll
                for (int mt = 0; mt < 2; mt++) {
                    ap[mt][0] = h2pack(Sc[mt][2*j][0],   Sc[mt][2*j][1]);
                    ap[mt][1] = h2pack(Sc[mt][2*j][2],   Sc[mt][2*j][3]);
                    ap[mt][2] = h2pack(Sc[mt][2*j+1][0], Sc[mt][2*j+1][1]);
                    ap[mt][3] = h2pack(Sc[mt][2*j+1][2], Sc[mt][2*j+1][3]);
                }
#pragma unroll
                for (int ntd = 0; ntd < 8; ntd++) {
                    const uint2 vv = *(const uint2*)
                        &V_[(j * 4 + tg) * VST3 + (ntd * 8 + gr) * 2];
                    mma_f16(Of[0][ntd], ap[0], (const uint32_t*)&vv);
                    mma_f16(Of[1][ntd], ap[1], (const uint32_t*)&vv);
                }
            }
        }

#pragma unroll
        for (int mt = 0; mt < 2; mt++)
#pragma unroll
            for (int nt = 0; nt < 4; nt++)
#pragma unroll
                for (int r = 0; r < 4; r++) Sc[mt][nt][r] = Sn[mt][nt][r];
    }
#undef KISSUE
#undef QK_TILE

    // epilogue -> concat, half pair-interleaved along d
    float inv[2][2];
#pragma unroll
    for (int mt = 0; mt < 2; mt++) {
        inv[mt][0] = 1.f / l_[mt][0];
        inv[mt][1] = 1.f / l_[mt][1];
    }
    const int b_ = bh >> 4, h_ = bh & 15;
#pragma unroll
    for (int mt = 0; mt < 2; mt++) {
        const int r0 = q0 + wq * 32 + mt * 16 + gr;
        uint32_t* o0 = g_scratch + OFF_CAT + ((size_t)(b_ * Ss + r0)) * 512 + h_ * 32;
        uint32_t* o1 = g_scratch + OFF_CAT + ((size_t)(b_ * Ss + r0 + 8)) * 512 + h_ * 32;
#pragma unroll
        for (int ntd = 0; ntd < 8; ntd++) {
            const int q_l = (ntd & 1) * 4 + tg;
            const int upos = (ntd >> 1) * 8 + 2 * (q_l & 3) + (q_l >> 2);
            o0[upos] = h2pack(Of[mt][ntd][0] * inv[mt][0],
                              Of[mt][ntd][1] * inv[mt][0]);
            o1[upos] = h2pack(Of[mt][ntd][2] * inv[mt][1],
                              Of[mt][ntd][3] * inv[mt][1]);
        }
    }
}

// ---------------------------------------------------------------------------
extern "C" void kernel_launch(void* const* d_in, const int* in_sizes, int n_in,
                              void* d_out, int out_size)
{
    const float* q_in = (const float*)d_in[0];
    const float* k_in = (const float*)d_in[1];
    const float* v_in = (const float*)d_in[2];
    const float* Wq   = (const float*)d_in[3];
    const float* bq   = (const float*)d_in[4];
    const float* Wk   = (const float*)d_in[5];
    const float* bk   = (const float*)d_in[6];
    const float* Wv   = (const float*)d_in[7];
    const float* bv   = (const float*)d_in[8];
    const float* Wo   = (const float*)d_in[9];
    const float* bo   = (const float*)d_in[10];
    float* out = (float*)d_out;

    cudaFuncSetAttribute(gemm_qkv_mma_kernel,
                         cudaFuncAttributeMaxDynamicSharedMemorySize, GEMM_SMEM_BYTES);
    cudaFuncSetAttribute(gemm_out_mma_kernel,
                         cudaFuncAttributeMaxDynamicSharedMemorySize, GEMM_SMEM_BYTES);
    cudaFuncSetAttribute(attn_mma_kernel,
                         cudaFuncAttributeMaxDynamicSharedMemorySize, ATTN_SMEM_BYTES);

    round_inputs_kernel<<<dim3(QKV_ELEMS / 4096, 3), 256>>>(q_in, k_in, v_in);
    transpose_w_kernel<<<dim3(32, 32, 4), dim3(32, 8)>>>(Wq, Wk, Wv, Wo);

    gemm_qkv_mma_kernel<<<dim3(8, 16, 3), 256, GEMM_SMEM_BYTES>>>(bq, bk, bv);

    repack_v_kernel<<<QKV_U32 / 256, 256>>>();

    attn_mma_kernel<<<512, 128, ATTN_SMEM_BYTES>>>();

    gemm_out_mma_kernel<<<dim3(8, 16), 256, GEMM_SMEM_BYTES>>>(bo, out);
}

// round 15
// speedup vs baseline: 1.1215x; 1.0282x over previous
#include <cuda_runtime.h>
#include <cstdint>

#define Bb 2
#define Ss 2048
#define Dd 1024
#define Hh 16
#define HDd 64
#define QKV_ELEMS (Bb*Hh*Ss*HDd)   // 4194304 halves per tensor
#define QKV_U32 (QKV_ELEMS/2)      // 2097152 u32
#define WT_U32 ((Dd*Dd)/2)         // 524288 u32

// u32 regions: q,k,v (pair-interleaved half), Vq (pair-of-pairs), concat,
// WT x4 (interleaved half), rounded inputs x3 (interleaved half)
#define OFF_QKV 0ull
#define OFF_VP  (3ull*QKV_U32)
#define OFF_CAT (4ull*QKV_U32)
#define OFF_WT  (5ull*QKV_U32)
#define OFF_AR  (5ull*QKV_U32 + 4ull*WT_U32)

static __device__ uint32_t g_scratch[8ull*QKV_U32 + 4ull*WT_U32];

#define QSC 0.18033688011112042f   // log2(e)/8

// ---------------------------------------------------------------------------
__device__ __forceinline__ uint32_t smem_u32(const void* p) {
    uint32_t a;
    asm("{ .reg .u64 t; cvta.to.shared.u64 t, %1; cvt.u32.u64 %0, t; }"
        : "=r"(a) : "l"(p));
    return a;
}
// pack two floats to f16x2: lo -> low 16 bits (PTX: first src -> high half)
__device__ __forceinline__ uint32_t h2pack(float lo, float hi) {
    uint32_t d;
    asm("cvt.rn.f16x2.f32 %0, %1, %2;" : "=r"(d) : "f"(hi), "f"(lo));
    return d;
}
__device__ __forceinline__ void mma_f16(float* c, const uint32_t* a, const uint32_t* b) {
    asm volatile(
        "mma.sync.aligned.m16n8k16.row.col.f32.f16.f16.f32 "
        "{%0,%1,%2,%3}, {%4,%5,%6,%7}, {%8,%9}, {%0,%1,%2,%3};"
        : "+f"(c[0]), "+f"(c[1]), "+f"(c[2]), "+f"(c[3])
        : "r"(a[0]), "r"(a[1]), "r"(a[2]), "r"(a[3]), "r"(b[0]), "r"(b[1]));
}
#define CP16(smem_addr, gptr) \
    asm volatile("cp.async.ca.shared.global [%0], [%1], 16;" \
                 :: "r"(smem_addr), "l"(gptr) : "memory")
#define CPCOMMIT() asm volatile("cp.async.commit_group;" ::: "memory")
#define CPWAIT(N)  asm volatile("cp.async.wait_group %0;" :: "n"(N) : "memory")

// ---------------------------------------------------------------------------
// Prep: fp32 -> f16x2, pair-interleaved within each 16-half k-group:
// phys u32 pos p holds half-pair q=(p>>1)+(p&1)*4, i.e. halves (2q,2q+1).
// ---------------------------------------------------------------------------
__global__ __launch_bounds__(256) void round_inputs_kernel(
    const float* __restrict__ q, const float* __restrict__ k,
    const float* __restrict__ v)
{
    const int z = blockIdx.y;
    const float* in = (z == 0) ? q : ((z == 1) ? k : v);
    uint32_t* out = g_scratch + OFF_AR + (size_t)z * QKV_U32;
    const size_t i = ((size_t)blockIdx.x * 256 + threadIdx.x) * 16;
    float vv[16];
#pragma unroll
    for (int j = 0; j < 16; j += 4)
        *(float4*)&vv[j] = *(const float4*)(in + i + j);
    const size_t ob = i >> 1;
#pragma unroll
    for (int p = 0; p < 8; p++) {
        const int qq = (p >> 1) + (p & 1) * 4;
        out[ob + p] = h2pack(vv[2 * qq], vv[2 * qq + 1]);
    }
}

// Weight transpose + half + pair-interleave; Wq additionally scaled by QSC.
__global__ __launch_bounds__(256) void transpose_w_kernel(
    const float* __restrict__ Wq, const float* __restrict__ Wk,
    const float* __restrict__ Wv, const float* __restrict__ Wo)
{
    __shared__ float t[32][33];
    const int z = blockIdx.z;
    const float* W = (z == 0) ? Wq : ((z == 1) ? Wk : ((z == 2) ? Wv : Wo));
    uint32_t* WT = g_scratch + OFF_WT + (size_t)z * WT_U32;
    const int x0 = blockIdx.x * 32, y0 = blockIdx.y * 32;
    const int tx = threadIdx.x, ty = threadIdx.y;
#pragma unroll
    for (int j = 0; j < 32; j += 8)
        t[ty + j][tx] = W[(size_t)(y0 + ty + j) * Dd + x0 + tx];
    __syncthreads();
    const float sc = (z == 0) ? QSC : 1.0f;
#pragma unroll
    for (int uu = 0; uu < 2; uu++) {
        const int u = ty * 2 + uu;               // u32 col within 16 (2 groups)
        const int g = u >> 3, p = u & 7;
        const int qq = (p >> 1) + (p & 1) * 4;
        const int k0 = g * 16 + 2 * qq;          // k-local half index
        const float a = t[k0][tx] * sc, b = t[k0 + 1][tx] * sc;
        WT[(size_t)(x0 + tx) * (Dd / 2) + (y0 >> 1) + u] = h2pack(a, b);
    }
}

// ---------------------------------------------------------------------------
// fp16 mma GEMM: CTA 256x128, warp 64x64 (8 warps 4x2), BK=32 halves (16 u32),
// 8-stage cp.async pipeline, packed stride-16-u32 tiles + ks-swap -> LDS.64.
// ---------------------------------------------------------------------------
#define GTA_U (256 * 16)          // 4096 u32
#define GTB_U (128 * 16)          // 2048
#define GSTAGE_U (GTA_U + GTB_U)  // 6144
#define GNSTAGE 8
#define GEMM_SMEM_BYTES (GNSTAGE * GSTAGE_U * 4)   // 196608

template<int SPLIT>
__device__ __forceinline__ void gemm_mma(const uint32_t* __restrict__ A,
                                         const uint32_t* __restrict__ BT,
                                         const float* __restrict__ bias,
                                         float bsc, void* __restrict__ Cv)
{
    extern __shared__ uint32_t smu[];

    const int tid = threadIdx.x;
    const int wid = tid >> 5, lane = tid & 31;
    const int m0 = blockIdx.y * 256, n0 = blockIdx.x * 128;

    const int row0 = tid >> 2, c4 = tid & 3;
    const int swp = ((c4 >> 1) ^ ((row0 >> 1) & 1)) << 3;
    const uint32_t soBase = (uint32_t)(row0 * 16 + swp + (c4 & 1) * 4) * 4;
    const uint32_t soStep = 64 * 16 * 4;
    const uint32_t* gA0 = A  + (size_t)(m0 + row0) * 512 + c4 * 4;
    const uint32_t* gA1 = A  + (size_t)(m0 + row0 + 64) * 512 + c4 * 4;
    const uint32_t* gA2 = A  + (size_t)(m0 + row0 + 128) * 512 + c4 * 4;
    const uint32_t* gA3 = A  + (size_t)(m0 + row0 + 192) * 512 + c4 * 4;
    const uint32_t* gB0 = BT + (size_t)(n0 + row0) * 512 + c4 * 4;
    const uint32_t* gB1 = BT + (size_t)(n0 + row0 + 64) * 512 + c4 * 4;
    const uint32_t sbase = smem_u32(smu);

    const int wm = wid >> 1, wn = wid & 1;
    const int mbw = wm * 64, nbw = wn * 64;
    const int gr = lane >> 2, ck = lane & 3;

    float acc[4][8][4];
#pragma unroll
    for (int i = 0; i < 4; i++)
#pragma unroll
        for (int j = 0; j < 8; j++)
#pragma unroll
            for (int r = 0; r < 4; r++) acc[i][j][r] = 0.f;

#define GISSUE(buf, k0) do { \
        uint32_t a_ = sbase + (uint32_t)(buf) * (GSTAGE_U * 4); \
        uint32_t b_ = a_ + GTA_U * 4; \
        CP16(a_ + soBase,            gA0 + (k0)); \
        CP16(a_ + soBase + soStep,   gA1 + (k0)); \
        CP16(a_ + soBase + 2*soStep, gA2 + (k0)); \
        CP16(a_ + soBase + 3*soStep, gA3 + (k0)); \
        CP16(b_ + soBase,            gB0 + (k0)); \
        CP16(b_ + soBase + soStep,   gB1 + (k0)); \
        CPCOMMIT(); \
    } while (0)

    GISSUE(0, 0); GISSUE(1, 16); GISSUE(2, 32); GISSUE(3, 48);
    GISSUE(4, 64); GISSUE(5, 80); GISSUE(6, 96);

    const int NIT = 32;   // 1024 halves / 32 per iter
    const int swk = (gr >> 1) & 1;
    for (int it = 0; it < NIT; ++it) {
        CPWAIT(6);
        __syncthreads();
        if (it + 7 < NIT) GISSUE((it + 7) & 7, (it + 7) * 16);
        else CPCOMMIT();

        const uint32_t* SA = smu + (size_t)(it & 7) * GSTAGE_U;
        const uint32_t* SB = SA + GTA_U;
#pragma unroll
        for (int ks = 0; ks < 2; ks++) {
            const int ko = ((ks ^ swk) << 3) + 2 * ck;
            uint2 bfr[8];
#pragma unroll
            for (int nt = 0; nt < 8; nt++)
                bfr[nt] = *(const uint2*)&SB[(nbw + nt * 8 + gr) * 16 + ko];
#pragma unroll
            for (int mt = 0; mt < 4; mt++) {
                const int rb = (mbw + mt * 16 + gr) * 16 + ko;
                const uint2 a01 = *(const uint2*)&SA[rb];
                const uint2 a23 = *(const uint2*)&SA[rb + 8 * 16];
                uint32_t af[4] = {a01.x, a23.x, a01.y, a23.y};
#pragma unroll
                for (int nt = 0; nt < 8; nt++)
                    mma_f16(acc[mt][nt], af, (const uint32_t*)&bfr[nt]);
            }
        }
    }
#undef GISSUE

#pragma unroll
    for (int mt = 0; mt < 4; mt++) {
        const int row = m0 + mbw + mt * 16 + gr;
#pragma unroll
        for (int nt = 0; nt < 8; nt++) {
            const int cbase = n0 + nbw + nt * 8;
            const float2 bi = *(const float2*)(bias + cbase + 2 * ck);
            if (SPLIT) {
                uint32_t* C = (uint32_t*)Cv;
                const int h = cbase >> 6;
                const int dloc = cbase & 63;
                const int g = dloc >> 4;
                const int q_l = ((dloc >> 3) & 1) * 4 + ck;
                const int upos = g * 8 + 2 * (q_l & 3) + (q_l >> 2);
                const int b0_ = row >> 11, s0 = row & 2047;
                const int row1 = row + 8;
                const int b1_ = row1 >> 11, s1 = row1 & 2047;
                C[(((size_t)(b0_ * Hh + h)) * Ss + s0) * 32 + upos] =
                    h2pack(acc[mt][nt][0] + bi.x * bsc,
                           acc[mt][nt][1] + bi.y * bsc);
                C[(((size_t)(b1_ * Hh + h)) * Ss + s1) * 32 + upos] =
                    h2pack(acc[mt][nt][2] + bi.x * bsc,
                           acc[mt][nt][3] + bi.y * bsc);
            } else {
                float* C = (float*)Cv;
                const int col = cbase + 2 * ck;
                float2 v0, v1;
                v0.x = acc[mt][nt][0] + bi.x; v0.y = acc[mt][nt][1] + bi.y;
                v1.x = acc[mt][nt][2] + bi.x; v1.y = acc[mt][nt][3] + bi.y;
                *(float2*)&C[(size_t)row * Dd + col] = v0;
                *(float2*)&C[(size_t)(row + 8) * Dd + col] = v1;
            }
        }
    }
}

__global__ __launch_bounds__(256, 1) void gemm_qkv_mma_kernel(
    const float* __restrict__ bq, const float* __restrict__ bk,
    const float* __restrict__ bv)
{
    const int z = blockIdx.z;
    const uint32_t* A  = g_scratch + OFF_AR + (size_t)z * QKV_U32;
    const float* bias  = (z == 0) ? bq : ((z == 1) ? bk : bv);
    const uint32_t* BT = g_scratch + OFF_WT + (size_t)z * WT_U32;
    uint32_t* C = g_scratch + (size_t)z * QKV_U32;
    gemm_mma<1>(A, BT, bias, (z == 0) ? QSC : 1.0f, C);
}

__global__ __launch_bounds__(256, 1) void gemm_out_mma_kernel(
    const float* __restrict__ bo, float* __restrict__ out)
{
    const uint32_t* A  = g_scratch + OFF_CAT;
    const uint32_t* BT = g_scratch + OFF_WT + 3ull * WT_U32;
    gemm_mma<0>(A, BT, bo, 1.0f, out);
}

// ---------------------------------------------------------------------------
// V repack -> pair-of-pairs (see R12 comment; gmem layout unchanged).
// ---------------------------------------------------------------------------
__global__ __launch_bounds__(256) void repack_v_kernel()
{
    const uint32_t* in = g_scratch + 2ull * QKV_U32;   // V
    uint32_t* out = g_scratch + OFF_VP;
    const size_t o = (size_t)blockIdx.x * 256 + threadIdx.x;  // over QKV_U32
    const int bh = (int)(o >> 16);           // 65536 u32 per bh
    const int rem = (int)(o & 65535);
    const int T = rem >> 10;                 // 1024 u32 per tile
    const int r = (rem >> 7) & 7;
    const int d2 = rem & 127;
    const int d = d2 >> 1, p = d2 & 1;
    const int j = r >> 2, s = r & 3;
    const int kp = T * 16 + j * 8 + s + p * 4;
    const int g = d >> 4, hh = d & 15, qh = hh >> 1, sel = hh & 1;
    const int u = g * 8 + 2 * (qh & 3) + (qh >> 2);
    const size_t rbase = ((size_t)bh * Ss + 2 * kp) * 32 + u;
    const uint32_t X = in[rbase];            // key 2kp
    const uint32_t Y = in[rbase + 32];       // key 2kp+1
    const uint32_t lo = sel ? (X >> 16) : (X & 0xFFFFu);
    const uint32_t hi = sel ? (Y & 0xFFFF0000u) : (Y << 16);
    out[o] = lo | hi;
}

// ---------------------------------------------------------------------------
// fp16 MMA flash attention, causal, intra-warp pipelined. V pair-of-pairs,
// smem stride 136 (136 mod 32 = 8 -> conflict-free LDS.64 phases).
// Deferred l: thread-local partials, quad-reduced once at the epilogue.
// 2 CTAs/SM.
// ---------------------------------------------------------------------------
#define QST 40                        // Q/K row stride (u32)
#define SQ_U (128 * QST)              // 5120
#define SK_OFF SQ_U
#define SKB2 (32 * QST)               // 1280
#define VST3 136                      // V newrow stride (u32); 136%32==8
#define SV_OFF (SK_OFF + 2 * SKB2)    // 7680
#define SVB (8 * VST3)                // 1088
#define ATTN_SMEM_BYTES ((SV_OFF + 3 * SVB) * 4)   // 43776

__global__ __launch_bounds__(128, 2) void attn_mma_kernel()
{
    extern __shared__ uint32_t smu[];
    const int bx = blockIdx.x;
    const int qt = 15 - (bx >> 5);
    const int bh = bx & 31;
    const int q0 = qt * 128;
    const int tid = threadIdx.x;
    const int wq = tid >> 5, lane = tid & 31;
    const int gr = lane >> 2, tg = lane & 3;

    const uint32_t* Qp = g_scratch + ((size_t)bh * Ss + q0) * 32;
    const uint32_t* Kp = g_scratch + QKV_U32 + (size_t)bh * Ss * 32;
    const uint32_t* Vp = g_scratch + OFF_VP + (size_t)bh * 65536;

    const uint32_t smb = smem_u32(smu);

#define KISSUE(kbuf, vbuf, t0) do { \
        _Pragma("unroll") \
        for (int j_ = 0; j_ < 2; j_++) { \
            const int f_ = tid + j_ * 128; \
            const int rK = f_ >> 3; const int cK = (f_ & 7) * 4; \
            CP16(smb + (uint32_t)(SK_OFF + (kbuf)*SKB2 + rK*QST + cK) * 4, \
                 Kp + (size_t)((t0) + rK) * 32 + cK); \
            const int rV = f_ >> 5; const int cV = (f_ & 31) * 4; \
            CP16(smb + (uint32_t)(SV_OFF + (vbuf)*SVB + rV*VST3 + cV) * 4, \
                 Vp + (size_t)(((t0) >> 5) * 8 + rV) * 128 + cV); \
        } \
        CPCOMMIT(); \
    } while (0)

#define QK_TILE(S, kbuf) do { \
        const uint32_t* K_ = smu + SK_OFF + (kbuf) * SKB2; \
        const uint32_t* Q_ = smu; \
        _Pragma("unroll") \
        for (int mt_ = 0; mt_ < 2; mt_++) \
            _Pragma("unroll") \
            for (int nt_ = 0; nt_ < 4; nt_++) \
                _Pragma("unroll") \
                for (int r_ = 0; r_ < 4; r_++) S[mt_][nt_][r_] = 0.f; \
        _Pragma("unroll") \
        for (int kt_ = 0; kt_ < 4; kt_++) { \
            const int ko_ = kt_ * 8 + 2 * tg; \
            uint2 bkf_[4]; \
            _Pragma("unroll") \
            for (int nt_ = 0; nt_ < 4; nt_++) \
                bkf_[nt_] = *(const uint2*)&K_[(nt_ * 8 + gr) * QST + ko_]; \
            _Pragma("unroll") \
            for (int mt_ = 0; mt_ < 2; mt_++) { \
                const int rr_ = wq * 32 + mt_ * 16 + gr; \
                const uint2 a01_ = *(const uint2*)&Q_[rr_ * QST + ko_]; \
                const uint2 a23_ = *(const uint2*)&Q_[(rr_ + 8) * QST + ko_]; \
                uint32_t aq_[4] = {a01_.x, a23_.x, a01_.y, a23_.y}; \
                _Pragma("unroll") \
                for (int nt_ = 0; nt_ < 4; nt_++) \
                    mma_f16(S[mt_][nt_], aq_, (const uint32_t*)&bkf_[nt_]); \
            } \
        } \
    } while (0)

    // stage Q (8 chunks/thread) then first K/V tile
    {
#pragma unroll
        for (int j = 0; j < 8; j++) {
            const int f = tid + j * 128;
            const int r = f >> 3, c = (f & 7) * 4;
            CP16(smb + (uint32_t)(r * QST + c) * 4, Qp + (size_t)r * 32 + c);
        }
        CPCOMMIT();
    }
    KISSUE(0, 0, 0);

    float Of[2][8][4];
#pragma unroll
    for (int mt = 0; mt < 2; mt++)
#pragma unroll
        for (int nt = 0; nt < 8; nt++)
#pragma unroll
            for (int r = 0; r < 4; r++) Of[mt][nt][r] = 0.f;
    float m_[2][2] = {{-1e30f, -1e30f}, {-1e30f, -1e30f}};
    float l_[2][2] = {{0.f, 0.f}, {0.f, 0.f}};   // thread-local partials
    float Sc[2][4][4], Sn[2][4][4];

    const int ntiles = qt * 4 + 4;
    const int my_last = qt * 4 + wq;

    CPWAIT(0);
    __syncthreads();
    KISSUE(1, 1, 32);
    QK_TILE(Sc, 0);

    for (int it = 0; it < ntiles; it++) {
        CPWAIT(0);
        __syncthreads();
        if (it + 2 < ntiles) KISSUE((it + 2) & 1, (it + 2) % 3, (it + 2) * 32);

        const bool more = (it + 1 < ntiles) && (it + 1 <= my_last);
        if (more) QK_TILE(Sn, (it + 1) & 1);

        if (it <= my_last) {
            if (it == my_last) {
                const int t0k = it * 32;
#pragma unroll
                for (int mt = 0; mt < 2; mt++) {
                    const int r0 = q0 + wq * 32 + mt * 16 + gr;
#pragma unroll
                    for (int nt = 0; nt < 4; nt++) {
                        const int key = t0k + nt * 8 + 2 * tg;
                        if (key > r0)         Sc[mt][nt][0] = -1e30f;
                        if (key + 1 > r0)     Sc[mt][nt][1] = -1e30f;
                        if (key > r0 + 8)     Sc[mt][nt][2] = -1e30f;
                        if (key + 1 > r0 + 8) Sc[mt][nt][3] = -1e30f;
                    }
                }
            }

            // online softmax (log2 domain, fp32); max quad-reduced, l deferred
#pragma unroll
            for (int mt = 0; mt < 2; mt++)
#pragma unroll
                for (int h = 0; h < 2; h++) {
                    float tm = fmaxf(fmaxf(Sc[mt][0][2*h], Sc[mt][0][2*h+1]),
                                     fmaxf(Sc[mt][1][2*h], Sc[mt][1][2*h+1]));
                    tm = fmaxf(tm, fmaxf(fmaxf(Sc[mt][2][2*h], Sc[mt][2][2*h+1]),
                                         fmaxf(Sc[mt][3][2*h], Sc[mt][3][2*h+1])));
                    tm = fmaxf(tm, __shfl_xor_sync(0xffffffffu, tm, 1));
                    tm = fmaxf(tm, __shfl_xor_sync(0xffffffffu, tm, 2));
                    const float mnew = fmaxf(m_[mt][h], tm);
                    const float corr = exp2f(m_[mt][h] - mnew);
                    m_[mt][h] = mnew;
                    l_[mt][h] *= corr;
#pragma unroll
                    for (int nt = 0; nt < 8; nt++) {
                        Of[mt][nt][2*h]     *= corr;
                        Of[mt][nt][2*h + 1] *= corr;
                    }
                }

#pragma unroll
            for (int mt = 0; mt < 2; mt++)
#pragma unroll
                for (int nt = 0; nt < 4; nt++) {
                    const float p0 = exp2f(Sc[mt][nt][0] - m_[mt][0]);
                    const float p1 = exp2f(Sc[mt][nt][1] - m_[mt][0]);
                    const float p2 = exp2f(Sc[mt][nt][2] - m_[mt][1]);
                    const float p3 = exp2f(Sc[mt][nt][3] - m_[mt][1]);
                    l_[mt][0] += p0 + p1;
                    l_[mt][1] += p2 + p3;
                    Sc[mt][nt][0] = p0; Sc[mt][nt][1] = p1;
                    Sc[mt][nt][2] = p2; Sc[mt][nt][3] = p3;
                }

            // P @ V : P packed straight from C-fragments; V rows pair-packed
            const uint32_t* V_ = smu + SV_OFF + (it % 3) * SVB;
#pragma unroll
            for (int j = 0; j < 2; j++) {
                uint32_t ap[2][4];
#pragma unroll
                for (int mt = 0; mt < 2; mt++) {
                    ap[mt][0] = h2pack(Sc[mt][2*j][0],   Sc[mt][2*j][1]);
                    ap[mt][1] = h2pack(Sc[mt][2*j][2],   Sc[mt][2*j][3]);
                    ap[mt][2] = h2pack(Sc[mt][2*j+1][0], Sc[mt][2*j+1][1]);
                    ap[mt][3] = h2pack(Sc[mt][2*j+1][2], Sc[mt][2*j+1][3]);
                }
#pragma unroll
                for (int ntd = 0; ntd < 8; ntd++) {
                    const uint2 vv = *(const uint2*)
                        &V_[(j * 4 + tg) * VST3 + (ntd * 8 + gr) * 2];
                    mma_f16(Of[0][ntd], ap[0], (const uint32_t*)&vv);
                    mma_f16(Of[1][ntd], ap[1], (const uint32_t*)&vv);
                }
            }
        }

#pragma unroll
        for (int mt = 0; mt < 2; mt++)
#pragma unroll
            for (int nt = 0; nt < 4; nt++)
#pragma unroll
                for (int r = 0; r < 4; r++) Sc[mt][nt][r] = Sn[mt][nt][r];
    }
#undef KISSUE
#undef QK_TILE

    // epilogue: reduce deferred l across the quad, then write concat
    float inv[2][2];
#pragma unroll
    for (int mt = 0; mt < 2; mt++)
#pragma unroll
        for (int h = 0; h < 2; h++) {
            float r = l_[mt][h];
            r += __shfl_xor_sync(0xffffffffu, r, 1);
            r += __shfl_xor_sync(0xffffffffu, r, 2);
            inv[mt][h] = 1.f / r;
        }
    const int b_ = bh >> 4, h_ = bh & 15;
#pragma unroll
    for (int mt = 0; mt < 2; mt++) {
        const int r0 = q0 + wq * 32 + mt * 16 + gr;
        uint32_t* o0 = g_scratch + OFF_CAT + ((size_t)(b_ * Ss + r0)) * 512 + h_ * 32;
        uint32_t* o1 = g_scratch + OFF_CAT + ((size_t)(b_ * Ss + r0 + 8)) * 512 + h_ * 32;
#pragma unroll
        for (int ntd = 0; ntd < 8; ntd++) {
            const int q_l = (ntd & 1) * 4 + tg;
            const int upos = (ntd >> 1) * 8 + 2 * (q_l & 3) + (q_l >> 2);
            o0[upos] = h2pack(Of[mt][ntd][0] * inv[mt][0],
                              Of[mt][ntd][1] * inv[mt][0]);
            o1[upos] = h2pack(Of[mt][ntd][2] * inv[mt][1],
                              Of[mt][ntd][3] * inv[mt][1]);
        }
    }
}

// ---------------------------------------------------------------------------
extern "C" void kernel_launch(void* const* d_in, const int* in_sizes, int n_in,
                              void* d_out, int out_size)
{
    const float* q_in = (const float*)d_in[0];
    const float* k_in = (const float*)d_in[1];
    const float* v_in = (const float*)d_in[2];
    const float* Wq   = (const float*)d_in[3];
    const float* bq   = (const float*)d_in[4];
    const float* Wk   = (const float*)d_in[5];
    const float* bk   = (const float*)d_in[6];
    const float* Wv   = (const float*)d_in[7];
    const float* bv   = (const float*)d_in[8];
    const float* Wo   = (const float*)d_in[9];
    const float* bo   = (const float*)d_in[10];
    float* out = (float*)d_out;

    cudaFuncSetAttribute(gemm_qkv_mma_kernel,
                         cudaFuncAttributeMaxDynamicSharedMemorySize, GEMM_SMEM_BYTES);
    cudaFuncSetAttribute(gemm_out_mma_kernel,
                         cudaFuncAttributeMaxDynamicSharedMemorySize, GEMM_SMEM_BYTES);
    cudaFuncSetAttribute(attn_mma_kernel,
                         cudaFuncAttributeMaxDynamicSharedMemorySize, ATTN_SMEM_BYTES);

    round_inputs_kernel<<<dim3(QKV_ELEMS / 4096, 3), 256>>>(q_in, k_in, v_in);
    transpose_w_kernel<<<dim3(32, 32, 4), dim3(32, 8)>>>(Wq, Wk, Wv, Wo);

    gemm_qkv_mma_kernel<<<dim3(8, 16, 3), 256, GEMM_SMEM_BYTES>>>(bq, bk, bv);

    repack_v_kernel<<<QKV_U32 / 256, 256>>>();

    attn_mma_kernel<<<512, 128, ATTN_SMEM_BYTES>>>();

    gemm_out_mma_kernel<<<dim3(8, 16), 256, GEMM_SMEM_BYTES>>>(bo, out);
}

// round 16
// speedup vs baseline: 1.1491x; 1.0246x over previous
#include <cuda_runtime.h>
#include <cstdint>

#define Bb 2
#define Ss 2048
#define Dd 1024
#define Hh 16
#define HDd 64
#define QKV_ELEMS (Bb*Hh*Ss*HDd)   // 4194304 halves per tensor
#define QKV_U32 (QKV_ELEMS/2)      // 2097152 u32
#define WT_U32 ((Dd*Dd)/2)         // 524288 u32

// u32 regions: q,k,v (pair-interleaved half), Vq (pair-of-pairs), concat,
// WT x4 (interleaved half), rounded inputs x3 (interleaved half)
#define OFF_QKV 0ull
#define OFF_VP  (3ull*QKV_U32)
#define OFF_CAT (4ull*QKV_U32)
#define OFF_WT  (5ull*QKV_U32)
#define OFF_AR  (5ull*QKV_U32 + 4ull*WT_U32)

static __device__ uint32_t g_scratch[8ull*QKV_U32 + 4ull*WT_U32];

#define QSC 0.18033688011112042f   // log2(e)/8

// ---------------------------------------------------------------------------
__device__ __forceinline__ uint32_t smem_u32(const void* p) {
    uint32_t a;
    asm("{ .reg .u64 t; cvta.to.shared.u64 t, %1; cvt.u32.u64 %0, t; }"
        : "=r"(a) : "l"(p));
    return a;
}
// pack two floats to f16x2: lo -> low 16 bits (PTX: first src -> high half)
__device__ __forceinline__ uint32_t h2pack(float lo, float hi) {
    uint32_t d;
    asm("cvt.rn.f16x2.f32 %0, %1, %2;" : "=r"(d) : "f"(hi), "f"(lo));
    return d;
}
__device__ __forceinline__ void mma_f16(float* c, const uint32_t* a, const uint32_t* b) {
    asm volatile(
        "mma.sync.aligned.m16n8k16.row.col.f32.f16.f16.f32 "
        "{%0,%1,%2,%3}, {%4,%5,%6,%7}, {%8,%9}, {%0,%1,%2,%3};"
        : "+f"(c[0]), "+f"(c[1]), "+f"(c[2]), "+f"(c[3])
        : "r"(a[0]), "r"(a[1]), "r"(a[2]), "r"(a[3]), "r"(b[0]), "r"(b[1]));
}
#define CP16(smem_addr, gptr) \
    asm volatile("cp.async.ca.shared.global [%0], [%1], 16;" \
                 :: "r"(smem_addr), "l"(gptr) : "memory")
#define CPCOMMIT() asm volatile("cp.async.commit_group;" ::: "memory")
#define CPWAIT(N)  asm volatile("cp.async.wait_group %0;" :: "n"(N) : "memory")

// ---------------------------------------------------------------------------
// Merged prep: blockIdx.y 0..2 -> input round+interleave; 3..6 -> W transpose.
// Inputs: fp32 -> f16x2 pair-interleaved (u32 pos p holds halves of pair
// q=(p>>1)+(p&1)*4). Weights: transpose + half + interleave; Wq scaled by QSC.
// ---------------------------------------------------------------------------
__global__ __launch_bounds__(256) void prep_kernel(
    const float* __restrict__ q, const float* __restrict__ k,
    const float* __restrict__ v,
    const float* __restrict__ Wq, const float* __restrict__ Wk,
    const float* __restrict__ Wv, const float* __restrict__ Wo)
{
    __shared__ float t[32][33];
    const int z = blockIdx.y;
    if (z < 3) {
        const float* in = (z == 0) ? q : ((z == 1) ? k : v);
        uint32_t* out = g_scratch + OFF_AR + (size_t)z * QKV_U32;
        const size_t i = ((size_t)blockIdx.x * 256 + threadIdx.x) * 16;
        float vv[16];
#pragma unroll
        for (int j = 0; j < 16; j += 4)
            *(float4*)&vv[j] = *(const float4*)(in + i + j);
        const size_t ob = i >> 1;
#pragma unroll
        for (int p = 0; p < 8; p++) {
            const int qq = (p >> 1) + (p & 1) * 4;
            out[ob + p] = h2pack(vv[2 * qq], vv[2 * qq + 1]);
        }
    } else {
        const int wz = z - 3;
        const float* W = (wz == 0) ? Wq : ((wz == 1) ? Wk : ((wz == 2) ? Wv : Wo));
        uint32_t* WT = g_scratch + OFF_WT + (size_t)wz * WT_U32;
        const int bx = blockIdx.x;
        const int x0 = (bx & 31) * 32, y0 = (bx >> 5) * 32;
        const int tx = threadIdx.x & 31, ty = threadIdx.x >> 5;   // ty 0..7
#pragma unroll
        for (int j = 0; j < 32; j += 8)
            t[ty + j][tx] = W[(size_t)(y0 + ty + j) * Dd + x0 + tx];
        __syncthreads();
        const float sc = (wz == 0) ? QSC : 1.0f;
#pragma unroll
        for (int uu = 0; uu < 2; uu++) {
            const int u = ty * 2 + uu;
            const int g = u >> 3, p = u & 7;
            const int qq = (p >> 1) + (p & 1) * 4;
            const int k0 = g * 16 + 2 * qq;      // k-local half index
            const float a = t[k0][tx] * sc, b = t[k0 + 1][tx] * sc;
            WT[(size_t)(x0 + tx) * (Dd / 2) + (y0 >> 1) + u] = h2pack(a, b);
        }
    }
}

// ---------------------------------------------------------------------------
// fp16 mma GEMM: CTA 256x128, warp 64x64 (8 warps 4x2), BK=32 halves (16 u32),
// 8-stage cp.async pipeline, packed stride-16-u32 tiles + ks-swap -> LDS.64.
// ---------------------------------------------------------------------------
#define GTA_U (256 * 16)          // 4096 u32
#define GTB_U (128 * 16)          // 2048
#define GSTAGE_U (GTA_U + GTB_U)  // 6144
#define GNSTAGE 8
#define GEMM_SMEM_BYTES (GNSTAGE * GSTAGE_U * 4)   // 196608

template<int SPLIT>
__device__ __forceinline__ void gemm_mma(const uint32_t* __restrict__ A,
                                         const uint32_t* __restrict__ BT,
                                         const float* __restrict__ bias,
                                         float bsc, void* __restrict__ Cv)
{
    extern __shared__ uint32_t smu[];

    const int tid = threadIdx.x;
    const int wid = tid >> 5, lane = tid & 31;
    const int m0 = blockIdx.y * 256, n0 = blockIdx.x * 128;

    const int row0 = tid >> 2, c4 = tid & 3;
    const int swp = ((c4 >> 1) ^ ((row0 >> 1) & 1)) << 3;
    const uint32_t soBase = (uint32_t)(row0 * 16 + swp + (c4 & 1) * 4) * 4;
    const uint32_t soStep = 64 * 16 * 4;
    const uint32_t* gA0 = A  + (size_t)(m0 + row0) * 512 + c4 * 4;
    const uint32_t* gA1 = A  + (size_t)(m0 + row0 + 64) * 512 + c4 * 4;
    const uint32_t* gA2 = A  + (size_t)(m0 + row0 + 128) * 512 + c4 * 4;
    const uint32_t* gA3 = A  + (size_t)(m0 + row0 + 192) * 512 + c4 * 4;
    const uint32_t* gB0 = BT + (size_t)(n0 + row0) * 512 + c4 * 4;
    const uint32_t* gB1 = BT + (size_t)(n0 + row0 + 64) * 512 + c4 * 4;
    const uint32_t sbase = smem_u32(smu);

    const int wm = wid >> 1, wn = wid & 1;
    const int mbw = wm * 64, nbw = wn * 64;
    const int gr = lane >> 2, ck = lane & 3;

    float acc[4][8][4];
#pragma unroll
    for (int i = 0; i < 4; i++)
#pragma unroll
        for (int j = 0; j < 8; j++)
#pragma unroll
            for (int r = 0; r < 4; r++) acc[i][j][r] = 0.f;

#define GISSUE(buf, k0) do { \
        uint32_t a_ = sbase + (uint32_t)(buf) * (GSTAGE_U * 4); \
        uint32_t b_ = a_ + GTA_U * 4; \
        CP16(a_ + soBase,            gA0 + (k0)); \
        CP16(a_ + soBase + soStep,   gA1 + (k0)); \
        CP16(a_ + soBase + 2*soStep, gA2 + (k0)); \
        CP16(a_ + soBase + 3*soStep, gA3 + (k0)); \
        CP16(b_ + soBase,            gB0 + (k0)); \
        CP16(b_ + soBase + soStep,   gB1 + (k0)); \
        CPCOMMIT(); \
    } while (0)

    GISSUE(0, 0); GISSUE(1, 16); GISSUE(2, 32); GISSUE(3, 48);
    GISSUE(4, 64); GISSUE(5, 80); GISSUE(6, 96);

    const int NIT = 32;   // 1024 halves / 32 per iter
    const int swk = (gr >> 1) & 1;
    for (int it = 0; it < NIT; ++it) {
        CPWAIT(6);
        __syncthreads();
        if (it + 7 < NIT) GISSUE((it + 7) & 7, (it + 7) * 16);
        else CPCOMMIT();

        const uint32_t* SA = smu + (size_t)(it & 7) * GSTAGE_U;
        const uint32_t* SB = SA + GTA_U;
#pragma unroll
        for (int ks = 0; ks < 2; ks++) {
            const int ko = ((ks ^ swk) << 3) + 2 * ck;
            uint2 bfr[8];
#pragma unroll
            for (int nt = 0; nt < 8; nt++)
                bfr[nt] = *(const uint2*)&SB[(nbw + nt * 8 + gr) * 16 + ko];
#pragma unroll
            for (int mt = 0; mt < 4; mt++) {
                const int rb = (mbw + mt * 16 + gr) * 16 + ko;
                const uint2 a01 = *(const uint2*)&SA[rb];
                const uint2 a23 = *(const uint2*)&SA[rb + 8 * 16];
                uint32_t af[4] = {a01.x, a23.x, a01.y, a23.y};
#pragma unroll
                for (int nt = 0; nt < 8; nt++)
                    mma_f16(acc[mt][nt], af, (const uint32_t*)&bfr[nt]);
            }
        }
    }
#undef GISSUE

#pragma unroll
    for (int mt = 0; mt < 4; mt++) {
        const int row = m0 + mbw + mt * 16 + gr;
#pragma unroll
        for (int nt = 0; nt < 8; nt++) {
            const int cbase = n0 + nbw + nt * 8;
            const float2 bi = *(const float2*)(bias + cbase + 2 * ck);
            if (SPLIT) {
                uint32_t* C = (uint32_t*)Cv;
                const int h = cbase >> 6;
                const int dloc = cbase & 63;
                const int g = dloc >> 4;
                const int q_l = ((dloc >> 3) & 1) * 4 + ck;
                const int upos = g * 8 + 2 * (q_l & 3) + (q_l >> 2);
                const int b0_ = row >> 11, s0 = row & 2047;
                const int row1 = row + 8;
                const int b1_ = row1 >> 11, s1 = row1 & 2047;
                C[(((size_t)(b0_ * Hh + h)) * Ss + s0) * 32 + upos] =
                    h2pack(acc[mt][nt][0] + bi.x * bsc,
                           acc[mt][nt][1] + bi.y * bsc);
                C[(((size_t)(b1_ * Hh + h)) * Ss + s1) * 32 + upos] =
                    h2pack(acc[mt][nt][2] + bi.x * bsc,
                           acc[mt][nt][3] + bi.y * bsc);
            } else {
                float* C = (float*)Cv;
                const int col = cbase + 2 * ck;
                float2 v0, v1;
                v0.x = acc[mt][nt][0] + bi.x; v0.y = acc[mt][nt][1] + bi.y;
                v1.x = acc[mt][nt][2] + bi.x; v1.y = acc[mt][nt][3] + bi.y;
                *(float2*)&C[(size_t)row * Dd + col] = v0;
                *(float2*)&C[(size_t)(row + 8) * Dd + col] = v1;
            }
        }
    }
}

__global__ __launch_bounds__(256, 1) void gemm_qkv_mma_kernel(
    const float* __restrict__ bq, const float* __restrict__ bk,
    const float* __restrict__ bv)
{
    const int z = blockIdx.z;
    const uint32_t* A  = g_scratch + OFF_AR + (size_t)z * QKV_U32;
    const float* bias  = (z == 0) ? bq : ((z == 1) ? bk : bv);
    const uint32_t* BT = g_scratch + OFF_WT + (size_t)z * WT_U32;
    uint32_t* C = g_scratch + (size_t)z * QKV_U32;
    gemm_mma<1>(A, BT, bias, (z == 0) ? QSC : 1.0f, C);
}

__global__ __launch_bounds__(256, 1) void gemm_out_mma_kernel(
    const float* __restrict__ bo, float* __restrict__ out)
{
    const uint32_t* A  = g_scratch + OFF_CAT;
    const uint32_t* BT = g_scratch + OFF_WT + 3ull * WT_U32;
    gemm_mma<0>(A, BT, bo, 1.0f, out);
}

// ---------------------------------------------------------------------------
// V repack -> pair-of-pairs (gmem layout; see R12 comment).
// ---------------------------------------------------------------------------
__global__ __launch_bounds__(256) void repack_v_kernel()
{
    const uint32_t* in = g_scratch + 2ull * QKV_U32;   // V
    uint32_t* out = g_scratch + OFF_VP;
    const size_t o = (size_t)blockIdx.x * 256 + threadIdx.x;  // over QKV_U32
    const int bh = (int)(o >> 16);           // 65536 u32 per bh
    const int rem = (int)(o & 65535);
    const int T = rem >> 10;                 // 1024 u32 per tile
    const int r = (rem >> 7) & 7;
    const int d2 = rem & 127;
    const int d = d2 >> 1, p = d2 & 1;
    const int j = r >> 2, s = r & 3;
    const int kp = T * 16 + j * 8 + s + p * 4;
    const int g = d >> 4, hh = d & 15, qh = hh >> 1, sel = hh & 1;
    const int u = g * 8 + 2 * (qh & 3) + (qh >> 2);
    const size_t rbase = ((size_t)bh * Ss + 2 * kp) * 32 + u;
    const uint32_t X = in[rbase];            // key 2kp
    const uint32_t Y = in[rbase + 32];       // key 2kp+1
    const uint32_t lo = sel ? (X >> 16) : (X & 0xFFFFu);
    const uint32_t hi = sel ? (Y & 0xFFFF0000u) : (Y << 16);
    out[o] = lo | hi;
}

// ---------------------------------------------------------------------------
// fp16 MMA flash attention, causal, intra-warp pipelined with 64-key macro
// tiles: one barrier per 2 tiles, K/V in a uniform 6-slot ring (slot = t%6).
// Sc/Sn roles alternate across the tile pair (no fragment copies).
// V pair-of-pairs, stride 136 (conflict-free LDS.64). Deferred l. 2 CTAs/SM.
// ---------------------------------------------------------------------------
#define QST 40                        // Q/K row stride (u32)
#define SQ_U (128 * QST)              // 5120
#define SK_OFF SQ_U
#define SKB2 (32 * QST)               // 1280 (one K tile slot)
#define VST3 136                      // V newrow stride (u32); 136%32==8
#define SV_OFF (SK_OFF + 6 * SKB2)    // 12800
#define SVB (8 * VST3)                // 1088 (one V tile slot)
#define ATTN_SMEM_BYTES ((SV_OFF + 6 * SVB) * 4)   // 77312

__global__ __launch_bounds__(128, 2) void attn_mma_kernel()
{
    extern __shared__ uint32_t smu[];
    const int bx = blockIdx.x;
    const int qt = 15 - (bx >> 5);
    const int bh = bx & 31;
    const int q0 = qt * 128;
    const int tid = threadIdx.x;
    const int wq = tid >> 5, lane = tid & 31;
    const int gr = lane >> 2, tg = lane & 3;

    const uint32_t* Qp = g_scratch + ((size_t)bh * Ss + q0) * 32;
    const uint32_t* Kp = g_scratch + QKV_U32 + (size_t)bh * Ss * 32;
    const uint32_t* Vp = g_scratch + OFF_VP + (size_t)bh * 65536;

    const uint32_t smb = smem_u32(smu);

// load one 32-key K/V tile into ring slot (no commit)
#define KISSUE1(slot, t0) do { \
        _Pragma("unroll") \
        for (int j_ = 0; j_ < 2; j_++) { \
            const int f_ = tid + j_ * 128; \
            const int rK = f_ >> 3; const int cK = (f_ & 7) * 4; \
            CP16(smb + (uint32_t)(SK_OFF + (slot)*SKB2 + rK*QST + cK) * 4, \
                 Kp + (size_t)((t0) + rK) * 32 + cK); \
            const int rV = f_ >> 5; const int cV = (f_ & 31) * 4; \
            CP16(smb + (uint32_t)(SV_OFF + (slot)*SVB + rV*VST3 + cV) * 4, \
                 Vp + (size_t)(((t0) >> 5) * 8 + rV) * 128 + cV); \
        } \
    } while (0)

#define QK_TILE(S, slot) do { \
        const uint32_t* K_ = smu + SK_OFF + (slot) * SKB2; \
        const uint32_t* Q_ = smu; \
        _Pragma("unroll") \
        for (int mt_ = 0; mt_ < 2; mt_++) \
            _Pragma("unroll") \
            for (int nt_ = 0; nt_ < 4; nt_++) \
                _Pragma("unroll") \
                for (int r_ = 0; r_ < 4; r_++) S[mt_][nt_][r_] = 0.f; \
        _Pragma("unroll") \
        for (int kt_ = 0; kt_ < 4; kt_++) { \
            const int ko_ = kt_ * 8 + 2 * tg; \
            uint2 bkf_[4]; \
            _Pragma("unroll") \
            for (int nt_ = 0; nt_ < 4; nt_++) \
                bkf_[nt_] = *(const uint2*)&K_[(nt_ * 8 + gr) * QST + ko_]; \
            _Pragma("unroll") \
            for (int mt_ = 0; mt_ < 2; mt_++) { \
                const int rr_ = wq * 32 + mt_ * 16 + gr; \
                const uint2 a01_ = *(const uint2*)&Q_[rr_ * QST + ko_]; \
                const uint2 a23_ = *(const uint2*)&Q_[(rr_ + 8) * QST + ko_]; \
                uint32_t aq_[4] = {a01_.x, a23_.x, a01_.y, a23_.y}; \
                _Pragma("unroll") \
                for (int nt_ = 0; nt_ < 4; nt_++) \
                    mma_f16(S[mt_][nt_], aq_, (const uint32_t*)&bkf_[nt_]); \
            } \
        } \
    } while (0)

// mask (if diagonal) + online softmax + PV for one tile
#define SOFTMAX_PV(S, tile, vslot) do { \
        if ((tile) == my_last) { \
            const int t0k = (tile) * 32; \
            _Pragma("unroll") \
            for (int mt = 0; mt < 2; mt++) { \
                const int r0 = q0 + wq * 32 + mt * 16 + gr; \
                _Pragma("unroll") \
                for (int nt = 0; nt < 4; nt++) { \
                    const int key = t0k + nt * 8 + 2 * tg; \
                    if (key > r0)         S[mt][nt][0] = -1e30f; \
                    if (key + 1 > r0)     S[mt][nt][1] = -1e30f; \
                    if (key > r0 + 8)     S[mt][nt][2] = -1e30f; \
                    if (key + 1 > r0 + 8) S[mt][nt][3] = -1e30f; \
                } \
            } \
        } \
        _Pragma("unroll") \
        for (int mt = 0; mt < 2; mt++) \
            _Pragma("unroll") \
            for (int h = 0; h < 2; h++) { \
                float tm = fmaxf(fmaxf(S[mt][0][2*h], S[mt][0][2*h+1]), \
                                 fmaxf(S[mt][1][2*h], S[mt][1][2*h+1])); \
                tm = fmaxf(tm, fmaxf(fmaxf(S[mt][2][2*h], S[mt][2][2*h+1]), \
                                     fmaxf(S[mt][3][2*h], S[mt][3][2*h+1]))); \
                tm = fmaxf(tm, __shfl_xor_sync(0xffffffffu, tm, 1)); \
                tm = fmaxf(tm, __shfl_xor_sync(0xffffffffu, tm, 2)); \
                const float mnew = fmaxf(m_[mt][h], tm); \
                const float corr = exp2f(m_[mt][h] - mnew); \
                m_[mt][h] = mnew; \
                l_[mt][h] *= corr; \
                _Pragma("unroll") \
                for (int nt = 0; nt < 8; nt++) { \
                    Of[mt][nt][2*h]     *= corr; \
                    Of[mt][nt][2*h + 1] *= corr; \
                } \
            } \
        _Pragma("unroll") \
        for (int mt = 0; mt < 2; mt++) \
            _Pragma("unroll") \
            for (int nt = 0; nt < 4; nt++) { \
                const float p0 = exp2f(S[mt][nt][0] - m_[mt][0]); \
                const float p1 = exp2f(S[mt][nt][1] - m_[mt][0]); \
                const float p2 = exp2f(S[mt][nt][2] - m_[mt][1]); \
                const float p3 = exp2f(S[mt][nt][3] - m_[mt][1]); \
                l_[mt][0] += p0 + p1; \
                l_[mt][1] += p2 + p3; \
                S[mt][nt][0] = p0; S[mt][nt][1] = p1; \
                S[mt][nt][2] = p2; S[mt][nt][3] = p3; \
            } \
        const uint32_t* V_ = smu + SV_OFF + (vslot) * SVB; \
        _Pragma("unroll") \
        for (int j = 0; j < 2; j++) { \
            uint32_t ap[2][4]; \
            _Pragma("unroll") \
            for (int mt = 0; mt < 2; mt++) { \
                ap[mt][0] = h2pack(S[mt][2*j][0],   S[mt][2*j][1]); \
                ap[mt][1] = h2pack(S[mt][2*j][2],   S[mt][2*j][3]); \
                ap[mt][2] = h2pack(S[mt][2*j+1][0], S[mt][2*j+1][1]); \
                ap[mt][3] = h2pack(S[mt][2*j+1][2], S[mt][2*j+1][3]); \
            } \
            _Pragma("unroll") \
            for (int ntd = 0; ntd < 8; ntd++) { \
                const uint2 vv = *(const uint2*) \
                    &V_[(j * 4 + tg) * VST3 + (ntd * 8 + gr) * 2]; \
                mma_f16(Of[0][ntd], ap[0], (const uint32_t*)&vv); \
                mma_f16(Of[1][ntd], ap[1], (const uint32_t*)&vv); \
            } \
        } \
    } while (0)

    // stage Q (group), then macro-tile 0 (tiles 0,1) as one group
    {
#pragma unroll
        for (int j = 0; j < 8; j++) {
            const int f = tid + j * 128;
            const int r = f >> 3, c = (f & 7) * 4;
            CP16(smb + (uint32_t)(r * QST + c) * 4, Qp + (size_t)r * 32 + c);
        }
        CPCOMMIT();
    }
    KISSUE1(0, 0); KISSUE1(1, 32); CPCOMMIT();

    float Of[2][8][4];
#pragma unroll
    for (int mt = 0; mt < 2; mt++)
#pragma unroll
        for (int nt = 0; nt < 8; nt++)
#pragma unroll
            for (int r = 0; r < 4; r++) Of[mt][nt][r] = 0.f;
    float m_[2][2] = {{-1e30f, -1e30f}, {-1e30f, -1e30f}};
    float l_[2][2] = {{0.f, 0.f}, {0.f, 0.f}};   // thread-local partials
    float Sc[2][4][4], Sn[2][4][4];

    const int ntiles = qt * 4 + 4;      // even, >= 4
    const int nmac = ntiles >> 1;       // >= 2
    const int my_last = qt * 4 + wq;    // this warp's diagonal tile

    // prologue: macro0 resident, issue macro1 (tiles 2,3), QK tile0
    CPWAIT(0);
    __syncthreads();
    KISSUE1(2, 64); KISSUE1(3, 96); CPCOMMIT();
    QK_TILE(Sc, 0);

    for (int m = 0; m < nmac; m++) {
        CPWAIT(0);          // macro m+1 resident
        __syncthreads();
        if (m + 2 < nmac) {
            const int tI = 2 * m + 4;
            KISSUE1(tI % 6, tI * 32);
            KISSUE1((tI + 1) % 6, (tI + 1) * 32);
        }
        CPCOMMIT();

        const int a = 2 * m, b = a + 1;
        if (b <= my_last) QK_TILE(Sn, b % 6);
        if (a <= my_last) SOFTMAX_PV(Sc, a, a % 6);
        if (b + 1 <= my_last) QK_TILE(Sc, (b + 1) % 6);
        if (b <= my_last) SOFTMAX_PV(Sn, b, b % 6);
    }
#undef KISSUE1
#undef QK_TILE
#undef SOFTMAX_PV

    // epilogue: reduce deferred l across the quad, then write concat
    float inv[2][2];
#pragma unroll
    for (int mt = 0; mt < 2; mt++)
#pragma unroll
        for (int h = 0; h < 2; h++) {
            float r = l_[mt][h];
            r += __shfl_xor_sync(0xffffffffu, r, 1);
            r += __shfl_xor_sync(0xffffffffu, r, 2);
            inv[mt][h] = 1.f / r;
        }
    const int b_ = bh >> 4, h_ = bh & 15;
#pragma unroll
    for (int mt = 0; mt < 2; mt++) {
        const int r0 = q0 + wq * 32 + mt * 16 + gr;
        uint32_t* o0 = g_scratch + OFF_CAT + ((size_t)(b_ * Ss + r0)) * 512 + h_ * 32;
        uint32_t* o1 = g_scratch + OFF_CAT + ((size_t)(b_ * Ss + r0 + 8)) * 512 + h_ * 32;
#pragma unroll
        for (int ntd = 0; ntd < 8; ntd++) {
            const int q_l = (ntd & 1) * 4 + tg;
            const int upos = (ntd >> 1) * 8 + 2 * (q_l & 3) + (q_l >> 2);
            o0[upos] = h2pack(Of[mt][ntd][0] * inv[mt][0],
                              Of[mt][ntd][1] * inv[mt][0]);
            o1[upos] = h2pack(Of[mt][ntd][2] * inv[mt][1],
                              Of[mt][ntd][3] * inv[mt][1]);
        }
    }
}

// ---------------------------------------------------------------------------
extern "C" void kernel_launch(void* const* d_in, const int* in_sizes, int n_in,
                              void* d_out, int out_size)
{
    const float* q_in = (const float*)d_in[0];
    const float* k_in = (const float*)d_in[1];
    const float* v_in = (const float*)d_in[2];
    const float* Wq   = (const float*)d_in[3];
    const float* bq   = (const float*)d_in[4];
    const float* Wk   = (const float*)d_in[5];
    const float* bk   = (const float*)d_in[6];
    const float* Wv   = (const float*)d_in[7];
    const float* bv   = (const float*)d_in[8];
    const float* Wo   = (const float*)d_in[9];
    const float* bo   = (const float*)d_in[10];
    float* out = (float*)d_out;

    cudaFuncSetAttribute(gemm_qkv_mma_kernel,
                         cudaFuncAttributeMaxDynamicSharedMemorySize, GEMM_SMEM_BYTES);
    cudaFuncSetAttribute(gemm_out_mma_kernel,
                         cudaFuncAttributeMaxDynamicSharedMemorySize, GEMM_SMEM_BYTES);
    cudaFuncSetAttribute(attn_mma_kernel,
                         cudaFuncAttributeMaxDynamicSharedMemorySize, ATTN_SMEM_BYTES);

    prep_kernel<<<dim3(1024, 7), 256>>>(q_in, k_in, v_in, Wq, Wk, Wv, Wo);

    gemm_qkv_mma_kernel<<<dim3(8, 16, 3), 256, GEMM_SMEM_BYTES>>>(bq, bk, bv);

    repack_v_kernel<<<QKV_U32 / 256, 256>>>();

    attn_mma_kernel<<<512, 128, ATTN_SMEM_BYTES>>>();

    gemm_out_mma_kernel<<<dim3(8, 16), 256, GEMM_SMEM_BYTES>>>(bo, out);
}

// round 17
// speedup vs baseline: 1.1730x; 1.0208x over previous
#include <cuda_runtime.h>
#include <cstdint>

#define Bb 2
#define Ss 2048
#define Dd 1024
#define Hh 16
#define HDd 64
#define QKV_ELEMS (Bb*Hh*Ss*HDd)   // 4194304 halves per tensor
#define QKV_U32 (QKV_ELEMS/2)      // 2097152 u32
#define WT_U32 ((Dd*Dd)/2)         // 524288 u32

// u32 regions: q,k,(v unused),Vq (pair-of-pairs),concat,WT x4,rounded inputs x3
#define OFF_QKV 0ull
#define OFF_VP  (3ull*QKV_U32)
#define OFF_CAT (4ull*QKV_U32)
#define OFF_WT  (5ull*QKV_U32)
#define OFF_AR  (5ull*QKV_U32 + 4ull*WT_U32)

static __device__ uint32_t g_scratch[8ull*QKV_U32 + 4ull*WT_U32];

#define QSC 0.18033688011112042f   // log2(e)/8

// ---------------------------------------------------------------------------
__device__ __forceinline__ uint32_t smem_u32(const void* p) {
    uint32_t a;
    asm("{ .reg .u64 t; cvta.to.shared.u64 t, %1; cvt.u32.u64 %0, t; }"
        : "=r"(a) : "l"(p));
    return a;
}
// pack two floats to f16x2: lo -> low 16 bits (PTX: first src -> high half)
__device__ __forceinline__ uint32_t h2pack(float lo, float hi) {
    uint32_t d;
    asm("cvt.rn.f16x2.f32 %0, %1, %2;" : "=r"(d) : "f"(hi), "f"(lo));
    return d;
}
__device__ __forceinline__ void mma_f16(float* c, const uint32_t* a, const uint32_t* b) {
    asm volatile(
        "mma.sync.aligned.m16n8k16.row.col.f32.f16.f16.f32 "
        "{%0,%1,%2,%3}, {%4,%5,%6,%7}, {%8,%9}, {%0,%1,%2,%3};"
        : "+f"(c[0]), "+f"(c[1]), "+f"(c[2]), "+f"(c[3])
        : "r"(a[0]), "r"(a[1]), "r"(a[2]), "r"(a[3]), "r"(b[0]), "r"(b[1]));
}
#define CP16(smem_addr, gptr) \
    asm volatile("cp.async.ca.shared.global [%0], [%1], 16;" \
                 :: "r"(smem_addr), "l"(gptr) : "memory")
#define CPCOMMIT() asm volatile("cp.async.commit_group;" ::: "memory")
#define CPWAIT(N)  asm volatile("cp.async.wait_group %0;" :: "n"(N) : "memory")

// ---------------------------------------------------------------------------
// Merged prep: blockIdx.y 0..2 -> input round+interleave; 3..6 -> W transpose.
// ---------------------------------------------------------------------------
__global__ __launch_bounds__(256) void prep_kernel(
    const float* __restrict__ q, const float* __restrict__ k,
    const float* __restrict__ v,
    const float* __restrict__ Wq, const float* __restrict__ Wk,
    const float* __restrict__ Wv, const float* __restrict__ Wo)
{
    __shared__ float t[32][33];
    const int z = blockIdx.y;
    if (z < 3) {
        const float* in = (z == 0) ? q : ((z == 1) ? k : v);
        uint32_t* out = g_scratch + OFF_AR + (size_t)z * QKV_U32;
        const size_t i = ((size_t)blockIdx.x * 256 + threadIdx.x) * 16;
        float vv[16];
#pragma unroll
        for (int j = 0; j < 16; j += 4)
            *(float4*)&vv[j] = *(const float4*)(in + i + j);
        const size_t ob = i >> 1;
#pragma unroll
        for (int p = 0; p < 8; p++) {
            const int qq = (p >> 1) + (p & 1) * 4;
            out[ob + p] = h2pack(vv[2 * qq], vv[2 * qq + 1]);
        }
    } else {
        const int wz = z - 3;
        const float* W = (wz == 0) ? Wq : ((wz == 1) ? Wk : ((wz == 2) ? Wv : Wo));
        uint32_t* WT = g_scratch + OFF_WT + (size_t)wz * WT_U32;
        const int bx = blockIdx.x;
        const int x0 = (bx & 31) * 32, y0 = (bx >> 5) * 32;
        const int tx = threadIdx.x & 31, ty = threadIdx.x >> 5;   // ty 0..7
#pragma unroll
        for (int j = 0; j < 32; j += 8)
            t[ty + j][tx] = W[(size_t)(y0 + ty + j) * Dd + x0 + tx];
        __syncthreads();
        const float sc = (wz == 0) ? QSC : 1.0f;
#pragma unroll
        for (int uu = 0; uu < 2; uu++) {
            const int u = ty * 2 + uu;
            const int g = u >> 3, p = u & 7;
            const int qq = (p >> 1) + (p & 1) * 4;
            const int k0 = g * 16 + 2 * qq;      // k-local half index
            const float a = t[k0][tx] * sc, b = t[k0 + 1][tx] * sc;
            WT[(size_t)(x0 + tx) * (Dd / 2) + (y0 >> 1) + u] = h2pack(a, b);
        }
    }
}

// ---------------------------------------------------------------------------
// fp16 mma GEMM: CTA 256x128, warp 64x64 (8 warps 4x2), BK=32 halves (16 u32),
// 9-stage cp.async ring, macro-iterations of 2 k-steps per barrier.
// MODE 0: C float (d_out) + bias.
// MODE 1: C half, [B,H,S,32u32] pair-interleaved (q/k); bias scaled by bsc.
// MODE 2: C half, V pair-of-pairs layout (direct; replaces repack kernel).
// ---------------------------------------------------------------------------
#define GTA_U (256 * 16)          // 4096 u32
#define GTB_U (128 * 16)          // 2048
#define GSTAGE_U (GTA_U + GTB_U)  // 6144
#define GNSTAGE 9
#define GEMM_SMEM_BYTES (GNSTAGE * GSTAGE_U * 4)   // 221184

template<int MODE>
__device__ __forceinline__ void gemm_mma(const uint32_t* __restrict__ A,
                                         const uint32_t* __restrict__ BT,
                                         const float* __restrict__ bias,
                                         float bsc, void* __restrict__ Cv)
{
    extern __shared__ uint32_t smu[];

    const int tid = threadIdx.x;
    const int wid = tid >> 5, lane = tid & 31;
    const int m0 = blockIdx.y * 256, n0 = blockIdx.x * 128;

    const int row0 = tid >> 2, c4 = tid & 3;
    const int swp = ((c4 >> 1) ^ ((row0 >> 1) & 1)) << 3;
    const uint32_t soBase = (uint32_t)(row0 * 16 + swp + (c4 & 1) * 4) * 4;
    const uint32_t soStep = 64 * 16 * 4;
    const uint32_t* gA0 = A  + (size_t)(m0 + row0) * 512 + c4 * 4;
    const uint32_t* gA1 = A  + (size_t)(m0 + row0 + 64) * 512 + c4 * 4;
    const uint32_t* gA2 = A  + (size_t)(m0 + row0 + 128) * 512 + c4 * 4;
    const uint32_t* gA3 = A  + (size_t)(m0 + row0 + 192) * 512 + c4 * 4;
    const uint32_t* gB0 = BT + (size_t)(n0 + row0) * 512 + c4 * 4;
    const uint32_t* gB1 = BT + (size_t)(n0 + row0 + 64) * 512 + c4 * 4;
    const uint32_t sbase = smem_u32(smu);

    const int wm = wid >> 1, wn = wid & 1;
    const int mbw = wm * 64, nbw = wn * 64;
    const int gr = lane >> 2, ck = lane & 3;

    float acc[4][8][4];
#pragma unroll
    for (int i = 0; i < 4; i++)
#pragma unroll
        for (int j = 0; j < 8; j++)
#pragma unroll
            for (int r = 0; r < 4; r++) acc[i][j][r] = 0.f;

#define GISSUE(buf, k0) do { \
        uint32_t a_ = sbase + (uint32_t)(buf) * (GSTAGE_U * 4); \
        uint32_t b_ = a_ + GTA_U * 4; \
        CP16(a_ + soBase,            gA0 + (k0)); \
        CP16(a_ + soBase + soStep,   gA1 + (k0)); \
        CP16(a_ + soBase + 2*soStep, gA2 + (k0)); \
        CP16(a_ + soBase + 3*soStep, gA3 + (k0)); \
        CP16(b_ + soBase,            gB0 + (k0)); \
        CP16(b_ + soBase + soStep,   gB1 + (k0)); \
        CPCOMMIT(); \
    } while (0)

#define GCOMP(it) do { \
        const uint32_t* SA = smu + (size_t)((it) % GNSTAGE) * GSTAGE_U; \
        const uint32_t* SB = SA + GTA_U; \
        _Pragma("unroll") \
        for (int ks = 0; ks < 2; ks++) { \
            const int ko = ((ks ^ swk) << 3) + 2 * ck; \
            uint2 bfr[8]; \
            _Pragma("unroll") \
            for (int nt = 0; nt < 8; nt++) \
                bfr[nt] = *(const uint2*)&SB[(nbw + nt * 8 + gr) * 16 + ko]; \
            _Pragma("unroll") \
            for (int mt = 0; mt < 4; mt++) { \
                const int rb = (mbw + mt * 16 + gr) * 16 + ko; \
                const uint2 a01 = *(const uint2*)&SA[rb]; \
                const uint2 a23 = *(const uint2*)&SA[rb + 8 * 16]; \
                uint32_t af[4] = {a01.x, a23.x, a01.y, a23.y}; \
                _Pragma("unroll") \
                for (int nt = 0; nt < 8; nt++) \
                    mma_f16(acc[mt][nt], af, (const uint32_t*)&bfr[nt]); \
            } \
        } \
    } while (0)

    GISSUE(0, 0); GISSUE(1, 16); GISSUE(2, 32); GISSUE(3, 48);
    GISSUE(4, 64); GISSUE(5, 80); GISSUE(6, 96);

    const int swk = (gr >> 1) & 1;
    for (int m = 0; m < 16; ++m) {      // 32 k-steps, 2 per macro-iter
        CPWAIT(5);
        __syncthreads();
        const int t1 = 2 * m + 7, t2 = 2 * m + 8;
        if (t1 < 32) GISSUE(t1 % 9, t1 * 16); else CPCOMMIT();
        if (t2 < 32) GISSUE(t2 % 9, t2 * 16); else CPCOMMIT();
        GCOMP(2 * m);
        GCOMP(2 * m + 1);
    }
#undef GISSUE
#undef GCOMP

#pragma unroll
    for (int mt = 0; mt < 4; mt++) {
        const int row = m0 + mbw + mt * 16 + gr;
#pragma unroll
        for (int nt = 0; nt < 8; nt++) {
            const int cbase = n0 + nbw + nt * 8;
            const float2 bi = *(const float2*)(bias + cbase + 2 * ck);
            if (MODE == 1) {
                uint32_t* C = (uint32_t*)Cv;
                const int h = cbase >> 6;
                const int dloc = cbase & 63;
                const int g = dloc >> 4;
                const int q_l = ((dloc >> 3) & 1) * 4 + ck;
                const int upos = g * 8 + 2 * (q_l & 3) + (q_l >> 2);
                const int b0_ = row >> 11, s0 = row & 2047;
                const int row1 = row + 8;
                const int b1_ = row1 >> 11, s1 = row1 & 2047;
                C[(((size_t)(b0_ * Hh + h)) * Ss + s0) * 32 + upos] =
                    h2pack(acc[mt][nt][0] + bi.x * bsc,
                           acc[mt][nt][1] + bi.y * bsc);
                C[(((size_t)(b1_ * Hh + h)) * Ss + s1) * 32 + upos] =
                    h2pack(acc[mt][nt][2] + bi.x * bsc,
                           acc[mt][nt][3] + bi.y * bsc);
            } else if (MODE == 2) {
                // direct V pair-of-pairs: merge adjacent-key halves via shfl
                uint32_t* C = (uint32_t*)Cv;
                const int h = cbase >> 6;
                const int dl0 = (cbase & 63) + 2 * ck;
                const int myd = dl0 + (gr & 1);
                const int b0_ = row >> 11;
                const int kpl = (row & 2047) >> 1;        // local key-pair
                const int T = kpl >> 4;
                const int jj = (kpl >> 3) & 1;
                const int ss = kpl & 3;
                const uint32_t own0 = h2pack(acc[mt][nt][0] + bi.x,
                                             acc[mt][nt][1] + bi.y);
                const uint32_t own1 = h2pack(acc[mt][nt][2] + bi.x,
                                             acc[mt][nt][3] + bi.y);
                const uint32_t oth0 = __shfl_xor_sync(0xffffffffu, own0, 4);
                const uint32_t oth1 = __shfl_xor_sync(0xffffffffu, own1, 4);
                uint32_t u0, u1;
                if (!(gr & 1)) {
                    u0 = (own0 & 0xFFFFu) | (oth0 << 16);
                    u1 = (own1 & 0xFFFFu) | (oth1 << 16);
                } else {
                    u0 = (oth0 >> 16) | (own0 & 0xFFFF0000u);
                    u1 = (oth1 >> 16) | (own1 & 0xFFFF0000u);
                }
                const size_t base = ((size_t)(b0_ * Hh + h)) * 65536
                                  + T * 1024 + (jj * 4 + ss) * 128 + myd * 2;
                C[base]     = u0;   // p=0 (keys row,row+1)
                C[base + 1] = u1;   // p=1 (keys row+8,row+9)
            } else {
                float* C = (float*)Cv;
                const int col = cbase + 2 * ck;
                float2 v0, v1;
                v0.x = acc[mt][nt][0] + bi.x; v0.y = acc[mt][nt][1] + bi.y;
                v1.x = acc[mt][nt][2] + bi.x; v1.y = acc[mt][nt][3] + bi.y;
                *(float2*)&C[(size_t)row * Dd + col] = v0;
                *(float2*)&C[(size_t)(row + 8) * Dd + col] = v1;
            }
        }
    }
}

__global__ __launch_bounds__(256, 1) void gemm_qkv_mma_kernel(
    const float* __restrict__ bq, const float* __restrict__ bk,
    const float* __restrict__ bv)
{
    const int z = blockIdx.z;
    const uint32_t* A  = g_scratch + OFF_AR + (size_t)z * QKV_U32;
    const uint32_t* BT = g_scratch + OFF_WT + (size_t)z * WT_U32;
    if (z == 2) {
        gemm_mma<2>(A, BT, bv, 1.0f, g_scratch + OFF_VP);
    } else {
        const float* bias = (z == 0) ? bq : bk;
        uint32_t* C = g_scratch + (size_t)z * QKV_U32;
        gemm_mma<1>(A, BT, bias, (z == 0) ? QSC : 1.0f, C);
    }
}

__global__ __launch_bounds__(256, 1) void gemm_out_mma_kernel(
    const float* __restrict__ bo, float* __restrict__ out)
{
    const uint32_t* A  = g_scratch + OFF_CAT;
    const uint32_t* BT = g_scratch + OFF_WT + 3ull * WT_U32;
    gemm_mma<0>(A, BT, bo, 1.0f, out);
}

// ---------------------------------------------------------------------------
// fp16 MMA flash attention, causal, intra-warp pipelined with 64-key macro
// tiles: one barrier per 2 tiles, K/V in a uniform 6-slot ring (slot = t%6).
// V pair-of-pairs, stride 136 (conflict-free LDS.64). Deferred l. 2 CTAs/SM.
// ---------------------------------------------------------------------------
#define QST 40                        // Q/K row stride (u32)
#define SQ_U (128 * QST)              // 5120
#define SK_OFF SQ_U
#define SKB2 (32 * QST)               // 1280 (one K tile slot)
#define VST3 136                      // V newrow stride (u32); 136%32==8
#define SV_OFF (SK_OFF + 6 * SKB2)    // 12800
#define SVB (8 * VST3)                // 1088 (one V tile slot)
#define ATTN_SMEM_BYTES ((SV_OFF + 6 * SVB) * 4)   // 77312

__global__ __launch_bounds__(128, 2) void attn_mma_kernel()
{
    extern __shared__ uint32_t smu[];
    const int bx = blockIdx.x;
    const int qt = 15 - (bx >> 5);
    const int bh = bx & 31;
    const int q0 = qt * 128;
    const int tid = threadIdx.x;
    const int wq = tid >> 5, lane = tid & 31;
    const int gr = lane >> 2, tg = lane & 3;

    const uint32_t* Qp = g_scratch + ((size_t)bh * Ss + q0) * 32;
    const uint32_t* Kp = g_scratch + QKV_U32 + (size_t)bh * Ss * 32;
    const uint32_t* Vp = g_scratch + OFF_VP + (size_t)bh * 65536;

    const uint32_t smb = smem_u32(smu);

// load one 32-key K/V tile into ring slot (no commit)
#define KISSUE1(slot, t0) do { \
        _Pragma("unroll") \
        for (int j_ = 0; j_ < 2; j_++) { \
            const int f_ = tid + j_ * 128; \
            const int rK = f_ >> 3; const int cK = (f_ & 7) * 4; \
            CP16(smb + (uint32_t)(SK_OFF + (slot)*SKB2 + rK*QST + cK) * 4, \
                 Kp + (size_t)((t0) + rK) * 32 + cK); \
            const int rV = f_ >> 5; const int cV = (f_ & 31) * 4; \
            CP16(smb + (uint32_t)(SV_OFF + (slot)*SVB + rV*VST3 + cV) * 4, \
                 Vp + (size_t)(((t0) >> 5) * 8 + rV) * 128 + cV); \
        } \
    } while (0)

#define QK_TILE(S, slot) do { \
        const uint32_t* K_ = smu + SK_OFF + (slot) * SKB2; \
        const uint32_t* Q_ = smu; \
        _Pragma("unroll") \
        for (int mt_ = 0; mt_ < 2; mt_++) \
            _Pragma("unroll") \
            for (int nt_ = 0; nt_ < 4; nt_++) \
                _Pragma("unroll") \
                for (int r_ = 0; r_ < 4; r_++) S[mt_][nt_][r_] = 0.f; \
        _Pragma("unroll") \
        for (int kt_ = 0; kt_ < 4; kt_++) { \
            const int ko_ = kt_ * 8 + 2 * tg; \
            uint2 bkf_[4]; \
            _Pragma("unroll") \
            for (int nt_ = 0; nt_ < 4; nt_++) \
                bkf_[nt_] = *(const uint2*)&K_[(nt_ * 8 + gr) * QST + ko_]; \
            _Pragma("unroll") \
            for (int mt_ = 0; mt_ < 2; mt_++) { \
                const int rr_ = wq * 32 + mt_ * 16 + gr; \
                const uint2 a01_ = *(const uint2*)&Q_[rr_ * QST + ko_]; \
                const uint2 a23_ = *(const uint2*)&Q_[(rr_ + 8) * QST + ko_]; \
                uint32_t aq_[4] = {a01_.x, a23_.x, a01_.y, a23_.y}; \
                _Pragma("unroll") \
                for (int nt_ = 0; nt_ < 4; nt_++) \
                    mma_f16(S[mt_][nt_], aq_, (const uint32_t*)&bkf_[nt_]); \
            } \
        } \
    } while (0)

// mask (if diagonal) + online softmax + PV for one tile
#define SOFTMAX_PV(S, tile, vslot) do { \
        if ((tile) == my_last) { \
            const int t0k = (tile) * 32; \
            _Pragma("unroll") \
            for (int mt = 0; mt < 2; mt++) { \
                const int r0 = q0 + wq * 32 + mt * 16 + gr; \
                _Pragma("unroll") \
                for (int nt = 0; nt < 4; nt++) { \
                    const int key = t0k + nt * 8 + 2 * tg; \
                    if (key > r0)         S[mt][nt][0] = -1e30f; \
                    if (key + 1 > r0)     S[mt][nt][1] = -1e30f; \
                    if (key > r0 + 8)     S[mt][nt][2] = -1e30f; \
                    if (key + 1 > r0 + 8) S[mt][nt][3] = -1e30f; \
                } \
            } \
        } \
        _Pragma("unroll") \
        for (int mt = 0; mt < 2; mt++) \
            _Pragma("unroll") \
            for (int h = 0; h < 2; h++) { \
                float tm = fmaxf(fmaxf(S[mt][0][2*h], S[mt][0][2*h+1]), \
                                 fmaxf(S[mt][1][2*h], S[mt][1][2*h+1])); \
                tm = fmaxf(tm, fmaxf(fmaxf(S[mt][2][2*h], S[mt][2][2*h+1]), \
                                     fmaxf(S[mt][3][2*h], S[mt][3][2*h+1]))); \
                tm = fmaxf(tm, __shfl_xor_sync(0xffffffffu, tm, 1)); \
                tm = fmaxf(tm, __shfl_xor_sync(0xffffffffu, tm, 2)); \
                const float mnew = fmaxf(m_[mt][h], tm); \
                const float corr = exp2f(m_[mt][h] - mnew); \
                m_[mt][h] = mnew; \
                l_[mt][h] *= corr; \
                _Pragma("unroll") \
                for (int nt = 0; nt < 8; nt++) { \
                    Of[mt][nt][2*h]     *= corr; \
                    Of[mt][nt][2*h + 1] *= corr; \
                } \
            } \
        _Pragma("unroll") \
        for (int mt = 0; mt < 2; mt++) \
            _Pragma("unroll") \
            for (int nt = 0; nt < 4; nt++) { \
                const float p0 = exp2f(S[mt][nt][0] - m_[mt][0]); \
                const float p1 = exp2f(S[mt][nt][1] - m_[mt][0]); \
                const float p2 = exp2f(S[mt][nt][2] - m_[mt][1]); \
                const float p3 = exp2f(S[mt][nt][3] - m_[mt][1]); \
                l_[mt][0] += p0 + p1; \
                l_[mt][1] += p2 + p3; \
                S[mt][nt][0] = p0; S[mt][nt][1] = p1; \
                S[mt][nt][2] = p2; S[mt][nt][3] = p3; \
            } \
        const uint32_t* V_ = smu + SV_OFF + (vslot) * SVB; \
        _Pragma("unroll") \
        for (int j = 0; j < 2; j++) { \
            uint32_t ap[2][4]; \
            _Pragma("unroll") \
            for (int mt = 0; mt < 2; mt++) { \
                ap[mt][0] = h2pack(S[mt][2*j][0],   S[mt][2*j][1]); \
                ap[mt][1] = h2pack(S[mt][2*j][2],   S[mt][2*j][3]); \
                ap[mt][2] = h2pack(S[mt][2*j+1][0], S[mt][2*j+1][1]); \
                ap[mt][3] = h2pack(S[mt][2*j+1][2], S[mt][2*j+1][3]); \
            } \
            _Pragma("unroll") \
            for (int ntd = 0; ntd < 8; ntd++) { \
                const uint2 vv = *(const uint2*) \
                    &V_[(j * 4 + tg) * VST3 + (ntd * 8 + gr) * 2]; \
                mma_f16(Of[0][ntd], ap[0], (const uint32_t*)&vv); \
                mma_f16(Of[1][ntd], ap[1], (const uint32_t*)&vv); \
            } \
        } \
    } while (0)

    // stage Q (group), then macro-tile 0 (tiles 0,1) as one group
    {
#pragma unroll
        for (int j = 0; j < 8; j++) {
            const int f = tid + j * 128;
            const int r = f >> 3, c = (f & 7) * 4;
            CP16(smb + (uint32_t)(r * QST + c) * 4, Qp + (size_t)r * 32 + c);
        }
        CPCOMMIT();
    }
    KISSUE1(0, 0); KISSUE1(1, 32); CPCOMMIT();

    float Of[2][8][4];
#pragma unroll
    for (int mt = 0; mt < 2; mt++)
#pragma unroll
        for (int nt = 0; nt < 8; nt++)
#pragma unroll
            for (int r = 0; r < 4; r++) Of[mt][nt][r] = 0.f;
    float m_[2][2] = {{-1e30f, -1e30f}, {-1e30f, -1e30f}};
    float l_[2][2] = {{0.f, 0.f}, {0.f, 0.f}};   // thread-local partials
    float Sc[2][4][4], Sn[2][4][4];

    const int ntiles = qt * 4 + 4;      // even, >= 4
    const int nmac = ntiles >> 1;       // >= 2
    const int my_last = qt * 4 + wq;    // this warp's diagonal tile

    // prologue: macro0 resident, issue macro1 (tiles 2,3), QK tile0
    CPWAIT(0);
    __syncthreads();
    KISSUE1(2, 64); KISSUE1(3, 96); CPCOMMIT();
    QK_TILE(Sc, 0);

    for (int m = 0; m < nmac; m++) {
        CPWAIT(0);          // macro m+1 resident
        __syncthreads();
        if (m + 2 < nmac) {
            const int tI = 2 * m + 4;
            KISSUE1(tI % 6, tI * 32);
            KISSUE1((tI + 1) % 6, (tI + 1) * 32);
        }
        CPCOMMIT();

        const int a = 2 * m, b = a + 1;
        if (b <= my_last) QK_TILE(Sn, b % 6);
        if (a <= my_last) SOFTMAX_PV(Sc, a, a % 6);
        if (b + 1 <= my_last) QK_TILE(Sc, (b + 1) % 6);
        if (b <= my_last) SOFTMAX_PV(Sn, b, b % 6);
    }
#undef KISSUE1
#undef QK_TILE
#undef SOFTMAX_PV

    // epilogue: reduce deferred l across the quad, then write concat
    float inv[2][2];
#pragma unroll
    for (int mt = 0; mt < 2; mt++)
#pragma unroll
        for (int h = 0; h < 2; h++) {
            float r = l_[mt][h];
            r += __shfl_xor_sync(0xffffffffu, r, 1);
            r += __shfl_xor_sync(0xffffffffu, r, 2);
            inv[mt][h] = 1.f / r;
        }
    const int b_ = bh >> 4, h_ = bh & 15;
#pragma unroll
    for (int mt = 0; mt < 2; mt++) {
        const int r0 = q0 + wq * 32 + mt * 16 + gr;
        uint32_t* o0 = g_scratch + OFF_CAT + ((size_t)(b_ * Ss + r0)) * 512 + h_ * 32;
        uint32_t* o1 = g_scratch + OFF_CAT + ((size_t)(b_ * Ss + r0 + 8)) * 512 + h_ * 32;
#pragma unroll
        for (int ntd = 0; ntd < 8; ntd++) {
            const int q_l = (ntd & 1) * 4 + tg;
            const int upos = (ntd >> 1) * 8 + 2 * (q_l & 3) + (q_l >> 2);
            o0[upos] = h2pack(Of[mt][ntd][0] * inv[mt][0],
                              Of[mt][ntd][1] * inv[mt][0]);
            o1[upos] = h2pack(Of[mt][ntd][2] * inv[mt][1],
                              Of[mt][ntd][3] * inv[mt][1]);
        }
    }
}

// ---------------------------------------------------------------------------
extern "C" void kernel_launch(void* const* d_in, const int* in_sizes, int n_in,
                              void* d_out, int out_size)
{
    const float* q_in = (const float*)d_in[0];
    const float* k_in = (const float*)d_in[1];
    const float* v_in = (const float*)d_in[2];
    const float* Wq   = (const float*)d_in[3];
    const float* bq   = (const float*)d_in[4];
    const float* Wk   = (const float*)d_in[5];
    const float* bk   = (const float*)d_in[6];
    const float* Wv   = (const float*)d_in[7];
    const float* bv   = (const float*)d_in[8];
    const float* Wo   = (const float*)d_in[9];
    const float* bo   = (const float*)d_in[10];
    float* out = (float*)d_out;

    cudaFuncSetAttribute(gemm_qkv_mma_kernel,
                         cudaFuncAttributeMaxDynamicSharedMemorySize, GEMM_SMEM_BYTES);
    cudaFuncSetAttribute(gemm_out_mma_kernel,
                         cudaFuncAttributeMaxDynamicSharedMemorySize, GEMM_SMEM_BYTES);
    cudaFuncSetAttribute(attn_mma_kernel,
                         cudaFuncAttributeMaxDynamicSharedMemorySize, ATTN_SMEM_BYTES);

    prep_kernel<<<dim3(1024, 7), 256>>>(q_in, k_in, v_in, Wq, Wk, Wv, Wo);

    gemm_qkv_mma_kernel<<<dim3(8, 16, 3), 256, GEMM_SMEM_BYTES>>>(bq, bk, bv);

    attn_mma_kernel<<<512, 128, ATTN_SMEM_BYTES>>>();

    gemm_out_mma_kernel<<<dim3(8, 16), 256, GEMM_SMEM_BYTES>>>(bo, out);
}